// round 11
// baseline (speedup 1.0000x reference)
#include <cuda_runtime.h>
#include <cuda_fp16.h>
#include <math.h>
#include <stdint.h>

#define PP 8
#define TT 200
#define FF 512
#define CC 20
#define QQ 1024
#define NM (PP*CC)
typedef unsigned long long ULL;

// ------------------------- device scratch -------------------------
__device__ float g_means[NM*FF];
__device__ float g_tm[PP*FF];
__device__ float g_task[(size_t)PP*FF*FF];
__device__ float g_M[(size_t)NM*FF*FF];            // cov_reg -> L (in place)
__device__ float g_W[(size_t)NM*FF*FF];            // W = L^{-1} (fp32)
__device__ float g_quad[(size_t)PP*QQ*CC];
__device__ float g_Ymu[NM*FF];                     // y = W * mu (fp32 exact)
__device__ uint32_t g_Wh[(size_t)NM*FF*(FF/2)];    // fp16 pairs along k
__device__ uint32_t g_Xh[(size_t)PP*(FF/2)*QQ];    // [p][kp][q] fp16 pairs along k
__device__ int   g_members[CC*TT];
__device__ int   g_cnt[CC];
__device__ float g_icnts[CC], g_sclS[CC], g_sclT[CC];

// ------------------------- fp16 pack helper -------------------------
__device__ __forceinline__ uint32_t pack_h2(float x0, float x1){
    __half h0 = __float2half_rn(x0);
    __half h1 = __float2half_rn(x1);
    return (uint32_t)__half_as_ushort(h0) | ((uint32_t)__half_as_ushort(h1) << 16);
}

#define MMA_F16(c, a0,a1,a2,a3, b0,b1) \
    asm volatile("mma.sync.aligned.m16n8k16.row.col.f32.f16.f16.f32 " \
        "{%0,%1,%2,%3},{%4,%5,%6,%7},{%8,%9},{%0,%1,%2,%3};" \
        : "+f"(c[0]),"+f"(c[1]),"+f"(c[2]),"+f"(c[3]) \
        : "r"(a0),"r"(a1),"r"(a2),"r"(a3),"r"(b0),"r"(b1))

__device__ __forceinline__ void ldm4(uint32_t &r0, uint32_t &r1, uint32_t &r2, uint32_t &r3,
                                     uint32_t saddr){
    asm volatile("ldmatrix.sync.aligned.m8n8.x4.shared.b16 {%0,%1,%2,%3}, [%4];"
        : "=r"(r0), "=r"(r1), "=r"(r2), "=r"(r3) : "r"(saddr));
}
__device__ __forceinline__ uint32_t smem_u32(const void* p){
    uint32_t a;
    asm("{ .reg .u64 t; cvta.to.shared.u64 t, %1; cvt.u32.u64 %0, t; }" : "=r"(a) : "l"(p));
    return a;
}

// ------------------------- setup -------------------------
__global__ void setup_k(const int* __restrict__ lab_raw){
    if (threadIdx.x == 0 && blockIdx.x == 0){
        bool odd_all_zero = true;
        for (int t = 1; t < 200; t += 2) if (lab_raw[t] != 0) odd_all_zero = false;
        bool even_has_big = false;
        for (int t = 0; t < 200; t += 2) if (lab_raw[t] > 0) even_has_big = true;
        bool is64 = odd_all_zero && even_has_big;

        int cnt[CC];
        #pragma unroll
        for (int c = 0; c < CC; c++) cnt[c] = 0;
        for (int t = 0; t < TT; t++){
            int cc = is64 ? lab_raw[2*t] : lab_raw[t];
            if (cc < 0) cc = 0; if (cc >= CC) cc = CC-1;
            g_members[cc*TT + cnt[cc]] = t;
            cnt[cc]++;
        }
        for (int c = 0; c < CC; c++){
            g_cnt[c] = cnt[c];
            float cs  = fmaxf((float)cnt[c], 1.0f);
            g_icnts[c] = 1.0f / cs;
            float lam = cs / (cs + 1.0f);
            g_sclS[c] = lam / fmaxf((float)cnt[c] - 1.0f, 1.0f);
            g_sclT[c] = 1.0f - lam;
        }
    }
}

// ------------------------- class means -------------------------
__global__ void means_k(const float* __restrict__ sf){
    int pc = blockIdx.x;
    int p = pc / CC, c = pc % CC;
    int n = g_cnt[c];
    float ic = g_icnts[c];
    for (int f = threadIdx.x; f < FF; f += blockDim.x){
        float s = 0.0f;
        for (int m = 0; m < n; m++){
            int t = g_members[c*TT + m];
            s += sf[((size_t)p*TT + t)*FF + f];
        }
        g_means[(size_t)pc*FF + f] = s * ic;
    }
}

// ------------------------- task mean -------------------------
__global__ void tm_k(const float* __restrict__ sf){
    int p = blockIdx.x;
    for (int f = threadIdx.x; f < FF; f += blockDim.x){
        float s = 0.0f;
        for (int t = 0; t < TT; t++) s += sf[((size_t)p*TT + t)*FF + f];
        g_tm[p*FF + f] = s * (1.0f/TT);
    }
}

// ------------------------- task covariance -------------------------
__global__ void taskcov_k(const float* __restrict__ sf){
    int tile = blockIdx.x;          // 0..35 (tg<=tf)
    int p    = blockIdx.y;
    int tf = 0, rem = tile;
    while (rem >= tf+1){ rem -= tf+1; tf++; }
    int tg = rem;
    __shared__ float af[8][68], ag[8][68];
    int tid = threadIdx.x, tx = tid & 15, ty = tid >> 4;
    int r0 = ty*4, c0 = tx*4;
    float acc[4][4] = {};
    const float* tmv = g_tm + p*FF;
    for (int t0 = 0; t0 < TT; t0 += 8){
        __syncthreads();
        #pragma unroll
        for (int ii = 0; ii < 2; ii++){
            int idx = ii*256 + tid;
            int s = idx >> 6, f = idx & 63;
            const float* row = sf + ((size_t)p*TT + t0 + s)*FF;
            af[s][f] = row[tf*64 + f] - tmv[tf*64 + f];
            ag[s][f] = row[tg*64 + f] - tmv[tg*64 + f];
        }
        __syncthreads();
        #pragma unroll
        for (int s = 0; s < 8; s++){
            float a[4], b[4];
            #pragma unroll
            for (int i = 0; i < 4; i++) a[i] = af[s][r0+i];
            #pragma unroll
            for (int j = 0; j < 4; j++) b[j] = ag[s][c0+j];
            #pragma unroll
            for (int i = 0; i < 4; i++)
                #pragma unroll
                for (int j = 0; j < 4; j++) acc[i][j] += a[i]*b[j];
        }
    }
    const float inv = 1.0f/(TT-1);
    float* dst = g_task + (size_t)p*FF*FF;
    #pragma unroll
    for (int i = 0; i < 4; i++)
        #pragma unroll
        for (int j = 0; j < 4; j++){
            int fr = tf*64 + r0 + i, gc = tg*64 + c0 + j;
            float v = acc[i][j]*inv;
            dst[(size_t)fr*FF + gc] = v;
            dst[(size_t)gc*FF + fr] = v;
        }
}

// ------------------------- cov_reg -------------------------
__global__ void buildM_k(const float* __restrict__ sf){
    int tile = blockIdx.x;          // 0..35
    int pc   = blockIdx.y;
    int p = pc / CC, c = pc % CC;
    int tf = 0, rem = tile;
    while (rem >= tf+1){ rem -= tf+1; tf++; }
    int tg = rem;
    __shared__ float af[4][68], ag[4][68];
    int tid = threadIdx.x, tx = tid & 15, ty = tid >> 4;
    int r0 = ty*4, c0 = tx*4;
    float acc[4][4] = {};
    int n = g_cnt[c];
    const float* mu = g_means + (size_t)pc*FF;
    for (int m0 = 0; m0 < n; m0 += 4){
        __syncthreads();
        {
            int s = tid >> 6, f = tid & 63;
            int m = m0 + s;
            float va = 0.0f, vg = 0.0f;
            if (m < n){
                int t = g_members[c*TT + m];
                const float* row = sf + ((size_t)p*TT + t)*FF;
                va = row[tf*64 + f] - mu[tf*64 + f];
                vg = row[tg*64 + f] - mu[tg*64 + f];
            }
            af[s][f] = va; ag[s][f] = vg;
        }
        __syncthreads();
        #pragma unroll
        for (int s = 0; s < 4; s++){
            float a[4], b[4];
            #pragma unroll
            for (int i = 0; i < 4; i++) a[i] = af[s][r0+i];
            #pragma unroll
            for (int j = 0; j < 4; j++) b[j] = ag[s][c0+j];
            #pragma unroll
            for (int i = 0; i < 4; i++)
                #pragma unroll
                for (int j = 0; j < 4; j++) acc[i][j] += a[i]*b[j];
        }
    }
    float ss = g_sclS[c], st = g_sclT[c];
    float* dst = g_M + (size_t)pc*FF*FF;
    const float* tk = g_task + (size_t)p*FF*FF;
    #pragma unroll
    for (int i = 0; i < 4; i++)
        #pragma unroll
        for (int j = 0; j < 4; j++){
            int fr = tf*64 + r0 + i, gc = tg*64 + c0 + j;
            float v = ss*acc[i][j] + st*tk[(size_t)fr*FF + gc] + ((fr == gc) ? 1.0f : 0.0f);
            dst[(size_t)fr*FF + gc] = v;
            dst[(size_t)gc*FF + fr] = v;
        }
}

// -------- zero Wh in the upper-right 64x64 of each 128-diag block --------
__global__ void zeroWu_k(){
    int rb  = blockIdx.x;
    int mat = blockIdx.y;
    uint32_t* wh = g_Wh + (size_t)mat*FF*(FF/2);
    for (int e = threadIdx.x; e < 64*32; e += 256){
        int r = e >> 5, cp = e & 31;
        size_t o = (size_t)(rb*128 + r)*(FF/2) + rb*64 + 32 + cp;
        wh[o] = 0u;
    }
}

// -------- zero g_quad --------
__global__ void zeroquad_k(){
    size_t n = (size_t)PP*QQ*CC;
    for (size_t i = (size_t)blockIdx.x*blockDim.x + threadIdx.x; i < n;
         i += (size_t)gridDim.x*blockDim.x)
        g_quad[i] = 0.0f;
}

// ------------- 64x64 float4 tile helpers (pitch 17 float4 = 68 words) -------------
#define PTW 68
#define PT4 17
__device__ __forceinline__ void ldt4(float4* dst, const float* g, int tid){
    #pragma unroll
    for (int e = tid; e < 1024; e += 256){
        int r = e >> 4, c4 = e & 15;
        dst[r*PT4 + c4] = *(const float4*)&g[(size_t)r*FF + c4*4];
    }
}
__device__ __forceinline__ float dot4(float4 a, float4 b){
    return a.x*b.x + a.y*b.y + a.z*b.z + a.w*b.w;
}
// C[r][c] += A[r][k]*B[c][k]; rows ty*4+i, cols tx+16*j
__device__ __forceinline__ void g64_nt4(const float4* A, const float4* B,
                                        float acc[4][4], int ty, int tx){
    #pragma unroll 4
    for (int kq = 0; kq < 16; kq++){
        float4 a[4], b[4];
        #pragma unroll
        for (int i = 0; i < 4; i++) a[i] = A[(ty*4+i)*PT4 + kq];
        #pragma unroll
        for (int j = 0; j < 4; j++) b[j] = B[(tx+16*j)*PT4 + kq];
        #pragma unroll
        for (int i = 0; i < 4; i++)
            #pragma unroll
            for (int j = 0; j < 4; j++) acc[i][j] += dot4(a[i], b[j]);
    }
}
// C[r][c] += A[r][k]*B[k][c]; rows ty*4+i, cols 4*tx+j
__device__ __forceinline__ void g64_nn4(const float4* A, const float4* B,
                                        float acc[4][4], int ty, int tx){
    #pragma unroll 2
    for (int kq = 0; kq < 16; kq++){
        float4 a[4];
        #pragma unroll
        for (int i = 0; i < 4; i++) a[i] = A[(ty*4+i)*PT4 + kq];
        #pragma unroll
        for (int kk = 0; kk < 4; kk++){
            float4 b = B[(4*kq+kk)*PT4 + tx];
            float av[4];
            #pragma unroll
            for (int i = 0; i < 4; i++)
                av[i] = (kk == 0) ? a[i].x : (kk == 1) ? a[i].y : (kk == 2) ? a[i].z : a[i].w;
            #pragma unroll
            for (int i = 0; i < 4; i++){
                acc[i][0] += av[i]*b.x;
                acc[i][1] += av[i]*b.y;
                acc[i][2] += av[i]*b.z;
                acc[i][3] += av[i]*b.w;
            }
        }
    }
}

// -------------- Phase A step j: diag factor + tri-inverse + panel --------
__global__ void __launch_bounds__(256) diagpanel_k(int j){
    extern __shared__ float sm[];
    float* sA = sm;                 // 64*68 words
    float* sB = sm + 64*PTW;
    float* sC = sm + 2*64*PTW;
    float4* sB4 = (float4*)sB;
    float4* sC4 = (float4*)sC;
    int mat = blockIdx.x;
    float* M = g_M + (size_t)mat*FF*FF;
    float* W = g_W + (size_t)mat*FF*FF;
    int tid = threadIdx.x, tx = tid & 15, ty = tid >> 4;

    ldt4((float4*)sA, M + (size_t)(j*64)*FF + j*64, tid);
    __syncthreads();
    // LDL^T elimination (1 barrier per column)
    for (int k = 0; k < 64; k++){
        float pinv = 1.0f / sA[k*PTW+k];
        #pragma unroll 4
        for (int e = tid; e < 4096; e += 256){
            int r = e >> 6, cc = e & 63;
            if (r > k && cc > k && cc <= r)
                sA[r*PTW+cc] -= sA[r*PTW+k]*sA[cc*PTW+k]*pinv;
        }
        __syncthreads();
    }
    if (tid < 64) sC[tid] = rsqrtf(sA[tid*PTW+tid]);
    __syncthreads();
    #pragma unroll 4
    for (int e = tid; e < 4096; e += 256){
        int r = e >> 6, cc = e & 63;
        if (cc <= r) sA[r*PTW+cc] *= sC[cc];
    }
    __syncthreads();

    // triangular inverse of L_jj -> sB (4 lanes per column)
    #pragma unroll 4
    for (int e = tid; e < 4096; e += 256) sB[(e>>6)*PTW + (e&63)] = 0.0f;
    __syncthreads();
    {
        int c = tid >> 2, s = tid & 3;
        unsigned gmask = 0xFu << ((tid & 31) & ~3);
        float dv = 1.0f / sA[c*PTW+c];
        if (s == 0) sB[c*PTW+c] = dv;
        __syncwarp(gmask);
        for (int r = c+1; r < 64; r++){
            float part = 0.0f;
            for (int k2 = c + s; k2 < r; k2 += 4)
                part += sA[r*PTW+k2] * sB[k2*PTW+c];
            part += __shfl_xor_sync(gmask, part, 1);
            part += __shfl_xor_sync(gmask, part, 2);
            if (s == 0) sB[r*PTW+c] = -part / sA[r*PTW+r];
            __syncwarp(gmask);
        }
    }
    __syncthreads();
    // store Linv_jj into W (fp32) + fp16 split
    #pragma unroll 4
    for (int e = tid; e < 4096; e += 256){
        int r = e >> 6, cc = e & 63;
        W[(size_t)(j*64 + r)*FF + j*64 + cc] = sB[r*PTW+cc];
    }
    {
        uint32_t* wh = g_Wh + (size_t)mat*FF*(FF/2);
        for (int e = tid; e < 2048; e += 256){
            int r = e >> 5, cp = e & 31;
            size_t o = (size_t)(j*64 + r)*(FF/2) + j*32 + cp;
            wh[o] = pack_h2(sB[r*PTW + 2*cp], sB[r*PTW + 2*cp + 1]);
        }
    }
    // panel: L_ij = A_ij * Linv_jj^T (NT, cols tx+16*j2)
    for (int i = j+1; i < 8; i++){
        __syncthreads();
        ldt4(sC4, M + (size_t)(i*64)*FF + j*64, tid);
        __syncthreads();
        float acc[4][4] = {};
        g64_nt4(sC4, sB4, acc, ty, tx);
        #pragma unroll
        for (int ii = 0; ii < 4; ii++)
            #pragma unroll
            for (int j2 = 0; j2 < 4; j2++)
                M[(size_t)(i*64 + ty*4 + ii)*FF + j*64 + tx + 16*j2] = acc[ii][j2];
    }
}

// -------------- Phase A trailing -------------
__global__ void __launch_bounds__(256) trailing_k(int j){
    extern __shared__ float sm[];
    float4* sA4 = (float4*)sm;
    float4* sB4 = (float4*)(sm + 64*PTW);
    int mat = blockIdx.y;
    int t = blockIdx.x;
    int i = j+1, cnt = 1;
    while (t >= cnt){ t -= cnt; i++; cnt = i - j; }
    int kk = j+1 + t;
    float* M = g_M + (size_t)mat*FF*FF;
    int tid = threadIdx.x, tx = tid & 15, ty = tid >> 4;
    ldt4(sA4, M + (size_t)(i*64)*FF + j*64, tid);
    ldt4(sB4, M + (size_t)(kk*64)*FF + j*64, tid);
    __syncthreads();
    float acc[4][4] = {};
    g64_nt4(sA4, sB4, acc, ty, tx);
    #pragma unroll
    for (int ii = 0; ii < 4; ii++)
        #pragma unroll
        for (int j2 = 0; j2 < 4; j2++){
            size_t o = (size_t)(i*64 + ty*4 + ii)*FF + kk*64 + tx + 16*j2;
            M[o] -= acc[ii][j2];
        }
}

// -------------- Phase B (writes W fp32 + fp16 split) -------------
__global__ void __launch_bounds__(256) phaseB_k(){
    extern __shared__ float sm[];
    float* sA = sm;
    float* sC = sm + 2*64*PTW;
    float4* sA4 = (float4*)sA;
    float4* sB4 = (float4*)(sm + 64*PTW);
    float4* sC4 = (float4*)sC;
    int j   = blockIdx.x;
    int mat = blockIdx.y;
    float* M = g_M + (size_t)mat*FF*FF;
    float* W = g_W + (size_t)mat*FF*FF;
    uint32_t* wh = g_Wh + (size_t)mat*FF*(FF/2);
    int tid = threadIdx.x, tx = tid & 15, ty = tid >> 4;

    for (int i = j+1; i < 8; i++){
        float acc[4][4] = {};
        for (int k = j; k < i; k++){
            __syncthreads();
            ldt4(sA4, M + (size_t)(i*64)*FF + k*64, tid);
            ldt4(sB4, W + (size_t)(k*64)*FF + j*64, tid);
            __syncthreads();
            g64_nn4(sA4, sB4, acc, ty, tx);
        }
        __syncthreads();
        #pragma unroll
        for (int ii = 0; ii < 4; ii++){
            float4 v = {acc[ii][0], acc[ii][1], acc[ii][2], acc[ii][3]};
            sC4[(ty*4 + ii)*PT4 + tx] = v;
        }
        ldt4(sA4, W + (size_t)(i*64)*FF + i*64, tid);
        __syncthreads();
        float acc2[4][4] = {};
        g64_nn4(sA4, sC4, acc2, ty, tx);
        #pragma unroll
        for (int ii = 0; ii < 4; ii++){
            float v0 = -acc2[ii][0], v1 = -acc2[ii][1], v2 = -acc2[ii][2], v3 = -acc2[ii][3];
            float4 v = {v0, v1, v2, v3};
            size_t row = (size_t)(i*64 + ty*4 + ii);
            *(float4*)&W[row*FF + j*64 + 4*tx] = v;
            size_t o = row*(FF/2) + j*32 + 2*tx;
            wh[o]   = pack_h2(v0, v1);
            wh[o+1] = pack_h2(v2, v3);
        }
        __syncthreads();
    }
}

// ------------------------- queries -> fp16 pairs, transposed: [p][kp][q] -------------------------
__global__ void qsplit_k(const float* __restrict__ qf){
    __shared__ float sq[16][FF];
    int qb = blockIdx.x;           // 0..63 (16 queries each)
    int p  = blockIdx.y;
    int tid = threadIdx.x;
    for (int u = tid; u < 16*FF; u += 256){
        int qi = u / FF, f = u % FF;
        sq[qi][f] = qf[((size_t)p*QQ + qb*16 + qi)*FF + f];
    }
    __syncthreads();
    uint32_t* dh = g_Xh + (size_t)p*(FF/2)*QQ;
    for (int u = tid; u < 256*16; u += 256){
        int kp = u >> 4, qi = u & 15;
        dh[(size_t)kp*QQ + qb*16 + qi] = pack_h2(sq[qi][2*kp], sq[qi][2*kp+1]);
    }
}

// ------------------------- y = W * mu (fp32 exact, triangular) -------------------------
__global__ void ymu_k(){
    __shared__ float smu[FF];
    int pc = blockIdx.x;
    int tid = threadIdx.x, lane = tid & 31, wid = tid >> 5;
    const float* W = g_W + (size_t)pc*FF*FF;
    for (int f = tid; f < FF; f += 256) smu[f] = g_means[(size_t)pc*FF + f];
    __syncthreads();
    for (int r = wid; r < FF; r += 8){
        float s = 0.0f;
        for (int k = lane; k <= r; k += 32)
            s += W[(size_t)r*FF + k] * smu[k];
        #pragma unroll
        for (int o = 16; o; o >>= 1) s += __shfl_xor_sync(0xFFFFFFFFu, s, o);
        if (lane == 0) g_Ymu[pc*FF + r] = s;
    }
}

// ================= quad via single fp16 mma.sync: quad = || y - fp16(W)·fp16(x) ||^2 =====
// Grid (8 qtiles, 160 pc, 4 rb), 256 threads (8 warps: 2 m x 4 n), 2 CTAs/SM.
#define WPITCH 36
#define XPITCH 136
#define QMMA_SMEM (128*WPITCH*4 + 32*XPITCH*4 + 128*4)
__global__ void __launch_bounds__(256, 2) quadmma_k(){
    extern __shared__ uint32_t smu32[];
    uint32_t* sWh = smu32;
    uint32_t* sXh = sWh + 128*WPITCH;
    float*    red = (float*)(sXh + 32*XPITCH);
    int pc = blockIdx.y;
    int p = pc / CC, c = pc % CC;
    int qbase = blockIdx.x * 128;
    int rb = blockIdx.z;
    int tid = threadIdx.x, lane = tid & 31, wid = tid >> 5;
    int g = lane >> 2, t = lane & 3;
    int warpM = wid & 1, warpN = wid >> 1;
    int lm_row = (lane & 7) + ((lane >> 3) & 1)*8;
    int lm_col = (lane >> 4)*4;
    uint32_t sWh_b = smem_u32(sWh);
    const uint4* gwh4 = (const uint4*)(g_Wh + (size_t)pc*FF*(FF/2));
    const uint4* gxh4 = (const uint4*)(g_Xh + (size_t)p*(FF/2)*QQ + qbase);
    const float* ym = g_Ymu + pc*FF;

    if (tid < 128) red[tid] = 0.0f;
    float qs[8];
    #pragma unroll
    for (int j = 0; j < 8; j++) qs[j] = 0.0f;

    float acc[4][4][4];
    #pragma unroll
    for (int mi = 0; mi < 4; mi++)
        #pragma unroll
        for (int ni = 0; ni < 4; ni++)
            #pragma unroll
            for (int r = 0; r < 4; r++) acc[mi][ni][r] = 0.0f;

    int nch = 2*rb + 2;
    for (int ch = 0; ch < nch; ch++){
        int kp0 = ch*32;
        __syncthreads();
        // stage W (uint4): row r, 8 uint4 across 32 kp
        #pragma unroll
        for (int u = tid; u < 1024; u += 256){
            int r = u >> 3, c4 = u & 7;
            size_t go = (size_t)(rb*128 + r)*(FF/8) + (kp0 >> 2) + c4;
            *(uint4*)&sWh[r*WPITCH + c4*4] = gwh4[go];
        }
        // stage X (uint4): row kp, 32 uint4 across 128 q
        #pragma unroll
        for (int u = tid; u < 1024; u += 256){
            int kp = u >> 5, q4 = u & 31;
            size_t go = (size_t)(kp0 + kp)*(QQ/4) + q4;
            *(uint4*)&sXh[kp*XPITCH + q4*4] = gxh4[go];
        }
        __syncthreads();
        bool diag = (ch >= 2*rb);
        int kbase = (ch - 2*rb)*64;
        #pragma unroll
        for (int s = 0; s < 4; s++){
            uint32_t bh[4][2];
            #pragma unroll
            for (int ni = 0; ni < 4; ni++){
                int col = warpN*32 + ni*8 + g;
                bh[ni][0] = sXh[(8*s + t)*XPITCH + col];
                bh[ni][1] = sXh[(8*s + t + 4)*XPITCH + col];
            }
            #pragma unroll
            for (int mi = 0; mi < 4; mi++){
                if (diag && (warpM*64 + mi*16 + 16 <= kbase + 16*s)) continue;
                uint32_t off = (uint32_t)(((warpM*64 + mi*16 + lm_row)*WPITCH + 8*s + lm_col)*4);
                uint32_t ah0,ah1,ah2,ah3;
                ldm4(ah0,ah1,ah2,ah3, sWh_b + off);
                #pragma unroll
                for (int ni = 0; ni < 4; ni++)
                    MMA_F16(acc[mi][ni], ah0,ah1,ah2,ah3, bh[ni][0],bh[ni][1]);
            }
        }
    }
    // epilogue: qs += (y - z)^2 over this CTA's 128 rows
    #pragma unroll
    for (int mi = 0; mi < 4; mi++){
        int r1 = rb*128 + warpM*64 + mi*16 + g;
        float y1 = ym[r1], y2 = ym[r1 + 8];
        #pragma unroll
        for (int ni = 0; ni < 4; ni++){
            float d0 = y1 - acc[mi][ni][0];
            float d1 = y1 - acc[mi][ni][1];
            float d2 = y2 - acc[mi][ni][2];
            float d3 = y2 - acc[mi][ni][3];
            qs[2*ni]   += d0*d0 + d2*d2;
            qs[2*ni+1] += d1*d1 + d3*d3;
        }
    }

    #pragma unroll
    for (int j = 0; j < 8; j++)
        #pragma unroll
        for (int o = 4; o < 32; o <<= 1)
            qs[j] += __shfl_xor_sync(0xFFFFFFFFu, qs[j], o);
    if (lane < 4){
        #pragma unroll
        for (int j = 0; j < 8; j++){
            int ni = j >> 1, b = j & 1;
            int q = warpN*32 + ni*8 + 2*lane + b;
            atomicAdd(&red[q], qs[j]);
        }
    }
    __syncthreads();
    if (tid < 128)
        atomicAdd(&g_quad[((size_t)p*QQ + qbase + tid)*CC + c], red[tid]);
}

// ------------------------- final outputs -------------------------
__global__ void logits_k(float* out){
    int q = blockIdx.x;
    int c = threadIdx.x;
    if (c < CC){
        float s = 0.0f;
        #pragma unroll
        for (int p = 0; p < PP; p++) s += g_quad[((size_t)p*QQ + q)*CC + c];
        out[q*CC + c] = -s * (1.0f/PP);
    }
}
__global__ void copymeans_k(float* out){
    for (int i = blockIdx.x*blockDim.x + threadIdx.x; i < NM*FF; i += gridDim.x*blockDim.x)
        out[QQ*CC + i] = g_means[i];
}

// ------------------------- launch -------------------------
extern "C" void kernel_launch(void* const* d_in, const int* in_sizes, int n_in,
                              void* d_out, int out_size) {
    const float* sf  = (const float*)d_in[0];
    const int*   lab = (const int*)d_in[1];
    const float* qf  = (const float*)d_in[2];
    float* out = (float*)d_out;

    const int CHOL_SMEM = 3*64*PTW*(int)sizeof(float);   // 52224
    const int TR_SMEM   = 2*64*PTW*(int)sizeof(float);   // 34816
    cudaFuncSetAttribute(diagpanel_k, cudaFuncAttributeMaxDynamicSharedMemorySize, CHOL_SMEM);
    cudaFuncSetAttribute(phaseB_k,    cudaFuncAttributeMaxDynamicSharedMemorySize, CHOL_SMEM);
    cudaFuncSetAttribute(quadmma_k,   cudaFuncAttributeMaxDynamicSharedMemorySize, QMMA_SMEM);

    setup_k<<<1, 32>>>(lab);
    means_k<<<NM, 256>>>(sf);
    tm_k<<<PP, 256>>>(sf);
    qsplit_k<<<dim3(64, PP), 256>>>(qf);
    taskcov_k<<<dim3(36, PP), 256>>>(sf);
    buildM_k<<<dim3(36, NM), 256>>>(sf);
    zeroWu_k<<<dim3(4, NM), 256>>>();
    zeroquad_k<<<160, 256>>>();
    for (int j = 0; j < 8; j++){
        diagpanel_k<<<NM, 256, CHOL_SMEM>>>(j);
        int nt = (7-j)*(8-j)/2;
        if (nt > 0)
            trailing_k<<<dim3(nt, NM), 256, TR_SMEM>>>(j);
    }
    phaseB_k<<<dim3(7, NM), 256, CHOL_SMEM>>>();
    ymu_k<<<NM, 256>>>();
    quadmma_k<<<dim3(8, NM, 4), 256, QMMA_SMEM>>>();
    logits_k<<<QQ, 32>>>(out);
    if (out_size >= QQ*CC + NM*FF)
        copymeans_k<<<160, 512>>>(out);
}

// round 12
// speedup vs baseline: 1.5734x; 1.5734x over previous
#include <cuda_runtime.h>
#include <cuda_fp16.h>
#include <math.h>
#include <stdint.h>

#define PP 8
#define TT 200
#define FF 512
#define CC 20
#define QQ 1024
#define NM (PP*CC)
typedef unsigned long long ULL;

// ------------------------- device scratch -------------------------
__device__ float g_means[NM*FF];
__device__ float g_tm[PP*FF];
__device__ float g_task[(size_t)PP*FF*FF];
__device__ float g_M[(size_t)NM*FF*FF];            // cov_reg -> L (in place)
__device__ float g_W[(size_t)NM*FF*FF];            // W = L^{-1} (fp32)
__device__ float g_quad[(size_t)PP*QQ*CC];
__device__ float g_Ymu[NM*FF];                     // y = W * mu (fp32 exact)
__device__ uint32_t g_Wh[(size_t)NM*FF*(FF/2)];    // fp16 pairs along k
__device__ uint32_t g_Xh[(size_t)PP*(FF/2)*QQ];    // [p][kp][q] fp16 pairs along k
__device__ int   g_members[CC*TT];
__device__ int   g_cnt[CC];
__device__ float g_icnts[CC], g_sclS[CC], g_sclT[CC];

// ------------------------- fp16 pack helper -------------------------
__device__ __forceinline__ uint32_t pack_h2(float x0, float x1){
    __half h0 = __float2half_rn(x0);
    __half h1 = __float2half_rn(x1);
    return (uint32_t)__half_as_ushort(h0) | ((uint32_t)__half_as_ushort(h1) << 16);
}

#define MMA_F16(c, a0,a1,a2,a3, b0,b1) \
    asm volatile("mma.sync.aligned.m16n8k16.row.col.f32.f16.f16.f32 " \
        "{%0,%1,%2,%3},{%4,%5,%6,%7},{%8,%9},{%0,%1,%2,%3};" \
        : "+f"(c[0]),"+f"(c[1]),"+f"(c[2]),"+f"(c[3]) \
        : "r"(a0),"r"(a1),"r"(a2),"r"(a3),"r"(b0),"r"(b1))

__device__ __forceinline__ void ldm4(uint32_t &r0, uint32_t &r1, uint32_t &r2, uint32_t &r3,
                                     uint32_t saddr){
    asm volatile("ldmatrix.sync.aligned.m8n8.x4.shared.b16 {%0,%1,%2,%3}, [%4];"
        : "=r"(r0), "=r"(r1), "=r"(r2), "=r"(r3) : "r"(saddr));
}
__device__ __forceinline__ uint32_t smem_u32(const void* p){
    uint32_t a;
    asm("{ .reg .u64 t; cvta.to.shared.u64 t, %1; cvt.u32.u64 %0, t; }" : "=r"(a) : "l"(p));
    return a;
}

// ------------------------- setup -------------------------
__global__ void setup_k(const int* __restrict__ lab_raw){
    if (threadIdx.x == 0 && blockIdx.x == 0){
        bool odd_all_zero = true;
        for (int t = 1; t < 200; t += 2) if (lab_raw[t] != 0) odd_all_zero = false;
        bool even_has_big = false;
        for (int t = 0; t < 200; t += 2) if (lab_raw[t] > 0) even_has_big = true;
        bool is64 = odd_all_zero && even_has_big;

        int cnt[CC];
        #pragma unroll
        for (int c = 0; c < CC; c++) cnt[c] = 0;
        for (int t = 0; t < TT; t++){
            int cc = is64 ? lab_raw[2*t] : lab_raw[t];
            if (cc < 0) cc = 0; if (cc >= CC) cc = CC-1;
            g_members[cc*TT + cnt[cc]] = t;
            cnt[cc]++;
        }
        for (int c = 0; c < CC; c++){
            g_cnt[c] = cnt[c];
            float cs  = fmaxf((float)cnt[c], 1.0f);
            g_icnts[c] = 1.0f / cs;
            float lam = cs / (cs + 1.0f);
            g_sclS[c] = lam / fmaxf((float)cnt[c] - 1.0f, 1.0f);
            g_sclT[c] = 1.0f - lam;
        }
    }
}

// ------------------------- class means -------------------------
__global__ void means_k(const float* __restrict__ sf){
    int pc = blockIdx.x;
    int p = pc / CC, c = pc % CC;
    int n = g_cnt[c];
    float ic = g_icnts[c];
    for (int f = threadIdx.x; f < FF; f += blockDim.x){
        float s = 0.0f;
        for (int m = 0; m < n; m++){
            int t = g_members[c*TT + m];
            s += sf[((size_t)p*TT + t)*FF + f];
        }
        g_means[(size_t)pc*FF + f] = s * ic;
    }
}

// ------------------------- task mean -------------------------
__global__ void tm_k(const float* __restrict__ sf){
    int p = blockIdx.x;
    for (int f = threadIdx.x; f < FF; f += blockDim.x){
        float s = 0.0f;
        for (int t = 0; t < TT; t++) s += sf[((size_t)p*TT + t)*FF + f];
        g_tm[p*FF + f] = s * (1.0f/TT);
    }
}

// ------------------------- task covariance -------------------------
__global__ void taskcov_k(const float* __restrict__ sf){
    int tile = blockIdx.x;          // 0..35 (tg<=tf)
    int p    = blockIdx.y;
    int tf = 0, rem = tile;
    while (rem >= tf+1){ rem -= tf+1; tf++; }
    int tg = rem;
    __shared__ float af[8][68], ag[8][68];
    int tid = threadIdx.x, tx = tid & 15, ty = tid >> 4;
    int r0 = ty*4, c0 = tx*4;
    float acc[4][4] = {};
    const float* tmv = g_tm + p*FF;
    for (int t0 = 0; t0 < TT; t0 += 8){
        __syncthreads();
        #pragma unroll
        for (int ii = 0; ii < 2; ii++){
            int idx = ii*256 + tid;
            int s = idx >> 6, f = idx & 63;
            const float* row = sf + ((size_t)p*TT + t0 + s)*FF;
            af[s][f] = row[tf*64 + f] - tmv[tf*64 + f];
            ag[s][f] = row[tg*64 + f] - tmv[tg*64 + f];
        }
        __syncthreads();
        #pragma unroll
        for (int s = 0; s < 8; s++){
            float a[4], b[4];
            #pragma unroll
            for (int i = 0; i < 4; i++) a[i] = af[s][r0+i];
            #pragma unroll
            for (int j = 0; j < 4; j++) b[j] = ag[s][c0+j];
            #pragma unroll
            for (int i = 0; i < 4; i++)
                #pragma unroll
                for (int j = 0; j < 4; j++) acc[i][j] += a[i]*b[j];
        }
    }
    const float inv = 1.0f/(TT-1);
    float* dst = g_task + (size_t)p*FF*FF;
    #pragma unroll
    for (int i = 0; i < 4; i++)
        #pragma unroll
        for (int j = 0; j < 4; j++){
            int fr = tf*64 + r0 + i, gc = tg*64 + c0 + j;
            float v = acc[i][j]*inv;
            dst[(size_t)fr*FF + gc] = v;
            dst[(size_t)gc*FF + fr] = v;
        }
}

// ------------------------- cov_reg -------------------------
__global__ void buildM_k(const float* __restrict__ sf){
    int tile = blockIdx.x;          // 0..35
    int pc   = blockIdx.y;
    int p = pc / CC, c = pc % CC;
    int tf = 0, rem = tile;
    while (rem >= tf+1){ rem -= tf+1; tf++; }
    int tg = rem;
    __shared__ float af[4][68], ag[4][68];
    int tid = threadIdx.x, tx = tid & 15, ty = tid >> 4;
    int r0 = ty*4, c0 = tx*4;
    float acc[4][4] = {};
    int n = g_cnt[c];
    const float* mu = g_means + (size_t)pc*FF;
    for (int m0 = 0; m0 < n; m0 += 4){
        __syncthreads();
        {
            int s = tid >> 6, f = tid & 63;
            int m = m0 + s;
            float va = 0.0f, vg = 0.0f;
            if (m < n){
                int t = g_members[c*TT + m];
                const float* row = sf + ((size_t)p*TT + t)*FF;
                va = row[tf*64 + f] - mu[tf*64 + f];
                vg = row[tg*64 + f] - mu[tg*64 + f];
            }
            af[s][f] = va; ag[s][f] = vg;
        }
        __syncthreads();
        #pragma unroll
        for (int s = 0; s < 4; s++){
            float a[4], b[4];
            #pragma unroll
            for (int i = 0; i < 4; i++) a[i] = af[s][r0+i];
            #pragma unroll
            for (int j = 0; j < 4; j++) b[j] = ag[s][c0+j];
            #pragma unroll
            for (int i = 0; i < 4; i++)
                #pragma unroll
                for (int j = 0; j < 4; j++) acc[i][j] += a[i]*b[j];
        }
    }
    float ss = g_sclS[c], st = g_sclT[c];
    float* dst = g_M + (size_t)pc*FF*FF;
    const float* tk = g_task + (size_t)p*FF*FF;
    #pragma unroll
    for (int i = 0; i < 4; i++)
        #pragma unroll
        for (int j = 0; j < 4; j++){
            int fr = tf*64 + r0 + i, gc = tg*64 + c0 + j;
            float v = ss*acc[i][j] + st*tk[(size_t)fr*FF + gc] + ((fr == gc) ? 1.0f : 0.0f);
            dst[(size_t)fr*FF + gc] = v;
            dst[(size_t)gc*FF + fr] = v;
        }
}

// -------- zero Wh in the upper-right 64x64 of each 128-diag block --------
__global__ void zeroWu_k(){
    int rb  = blockIdx.x;
    int mat = blockIdx.y;
    uint32_t* wh = g_Wh + (size_t)mat*FF*(FF/2);
    for (int e = threadIdx.x; e < 64*32; e += 256){
        int r = e >> 5, cp = e & 31;
        size_t o = (size_t)(rb*128 + r)*(FF/2) + rb*64 + 32 + cp;
        wh[o] = 0u;
    }
}

// -------- zero g_quad --------
__global__ void zeroquad_k(){
    size_t n = (size_t)PP*QQ*CC;
    for (size_t i = (size_t)blockIdx.x*blockDim.x + threadIdx.x; i < n;
         i += (size_t)gridDim.x*blockDim.x)
        g_quad[i] = 0.0f;
}

// ------------- 64x64 float4 tile helpers (pitch 17 float4 = 68 words) -------------
#define PTW 68
#define PT4 17
__device__ __forceinline__ void ldt4(float4* dst, const float* g, int tid){
    #pragma unroll
    for (int e = tid; e < 1024; e += 256){
        int r = e >> 4, c4 = e & 15;
        dst[r*PT4 + c4] = *(const float4*)&g[(size_t)r*FF + c4*4];
    }
}
__device__ __forceinline__ float dot4(float4 a, float4 b){
    return a.x*b.x + a.y*b.y + a.z*b.z + a.w*b.w;
}
// C[r][c] += A[r][k]*B[c][k]; rows ty*4+i, cols tx+16*j
__device__ __forceinline__ void g64_nt4(const float4* A, const float4* B,
                                        float acc[4][4], int ty, int tx){
    #pragma unroll 4
    for (int kq = 0; kq < 16; kq++){
        float4 a[4], b[4];
        #pragma unroll
        for (int i = 0; i < 4; i++) a[i] = A[(ty*4+i)*PT4 + kq];
        #pragma unroll
        for (int j = 0; j < 4; j++) b[j] = B[(tx+16*j)*PT4 + kq];
        #pragma unroll
        for (int i = 0; i < 4; i++)
            #pragma unroll
            for (int j = 0; j < 4; j++) acc[i][j] += dot4(a[i], b[j]);
    }
}
// C[r][c] += A[r][k]*B[k][c]; rows ty*4+i, cols 4*tx+j
__device__ __forceinline__ void g64_nn4(const float4* A, const float4* B,
                                        float acc[4][4], int ty, int tx){
    #pragma unroll 2
    for (int kq = 0; kq < 16; kq++){
        float4 a[4];
        #pragma unroll
        for (int i = 0; i < 4; i++) a[i] = A[(ty*4+i)*PT4 + kq];
        #pragma unroll
        for (int kk = 0; kk < 4; kk++){
            float4 b = B[(4*kq+kk)*PT4 + tx];
            float av[4];
            #pragma unroll
            for (int i = 0; i < 4; i++)
                av[i] = (kk == 0) ? a[i].x : (kk == 1) ? a[i].y : (kk == 2) ? a[i].z : a[i].w;
            #pragma unroll
            for (int i = 0; i < 4; i++){
                acc[i][0] += av[i]*b.x;
                acc[i][1] += av[i]*b.y;
                acc[i][2] += av[i]*b.z;
                acc[i][3] += av[i]*b.w;
            }
        }
    }
}

// -------------- Phase A step j: diag factor + tri-inverse + panel --------
__global__ void __launch_bounds__(256) diagpanel_k(int j){
    extern __shared__ float sm[];
    float* sA = sm;                 // 64*68 words
    float* sB = sm + 64*PTW;
    float* sC = sm + 2*64*PTW;
    float4* sB4 = (float4*)sB;
    float4* sC4 = (float4*)sC;
    int mat = blockIdx.x;
    float* M = g_M + (size_t)mat*FF*FF;
    float* W = g_W + (size_t)mat*FF*FF;
    int tid = threadIdx.x, tx = tid & 15, ty = tid >> 4;

    ldt4((float4*)sA, M + (size_t)(j*64)*FF + j*64, tid);
    __syncthreads();
    // LDL^T elimination (1 barrier per column)
    for (int k = 0; k < 64; k++){
        float pinv = 1.0f / sA[k*PTW+k];
        #pragma unroll 4
        for (int e = tid; e < 4096; e += 256){
            int r = e >> 6, cc = e & 63;
            if (r > k && cc > k && cc <= r)
                sA[r*PTW+cc] -= sA[r*PTW+k]*sA[cc*PTW+k]*pinv;
        }
        __syncthreads();
    }
    if (tid < 64) sC[tid] = rsqrtf(sA[tid*PTW+tid]);
    __syncthreads();
    #pragma unroll 4
    for (int e = tid; e < 4096; e += 256){
        int r = e >> 6, cc = e & 63;
        if (cc <= r) sA[r*PTW+cc] *= sC[cc];
    }
    __syncthreads();

    // triangular inverse of L_jj -> sB (4 lanes per column)
    #pragma unroll 4
    for (int e = tid; e < 4096; e += 256) sB[(e>>6)*PTW + (e&63)] = 0.0f;
    __syncthreads();
    {
        int c = tid >> 2, s = tid & 3;
        unsigned gmask = 0xFu << ((tid & 31) & ~3);
        float dv = 1.0f / sA[c*PTW+c];
        if (s == 0) sB[c*PTW+c] = dv;
        __syncwarp(gmask);
        for (int r = c+1; r < 64; r++){
            float part = 0.0f;
            for (int k2 = c + s; k2 < r; k2 += 4)
                part += sA[r*PTW+k2] * sB[k2*PTW+c];
            part += __shfl_xor_sync(gmask, part, 1);
            part += __shfl_xor_sync(gmask, part, 2);
            if (s == 0) sB[r*PTW+c] = -part / sA[r*PTW+r];
            __syncwarp(gmask);
        }
    }
    __syncthreads();
    // store Linv_jj into W (fp32) + fp16 split
    #pragma unroll 4
    for (int e = tid; e < 4096; e += 256){
        int r = e >> 6, cc = e & 63;
        W[(size_t)(j*64 + r)*FF + j*64 + cc] = sB[r*PTW+cc];
    }
    {
        uint32_t* wh = g_Wh + (size_t)mat*FF*(FF/2);
        for (int e = tid; e < 2048; e += 256){
            int r = e >> 5, cp = e & 31;
            size_t o = (size_t)(j*64 + r)*(FF/2) + j*32 + cp;
            wh[o] = pack_h2(sB[r*PTW + 2*cp], sB[r*PTW + 2*cp + 1]);
        }
    }
    // panel: L_ij = A_ij * Linv_jj^T (NT, cols tx+16*j2)
    for (int i = j+1; i < 8; i++){
        __syncthreads();
        ldt4(sC4, M + (size_t)(i*64)*FF + j*64, tid);
        __syncthreads();
        float acc[4][4] = {};
        g64_nt4(sC4, sB4, acc, ty, tx);
        #pragma unroll
        for (int ii = 0; ii < 4; ii++)
            #pragma unroll
            for (int j2 = 0; j2 < 4; j2++)
                M[(size_t)(i*64 + ty*4 + ii)*FF + j*64 + tx + 16*j2] = acc[ii][j2];
    }
}

// -------------- Phase A trailing -------------
__global__ void __launch_bounds__(256) trailing_k(int j){
    extern __shared__ float sm[];
    float4* sA4 = (float4*)sm;
    float4* sB4 = (float4*)(sm + 64*PTW);
    int mat = blockIdx.y;
    int t = blockIdx.x;
    int i = j+1, cnt = 1;
    while (t >= cnt){ t -= cnt; i++; cnt = i - j; }
    int kk = j+1 + t;
    float* M = g_M + (size_t)mat*FF*FF;
    int tid = threadIdx.x, tx = tid & 15, ty = tid >> 4;
    ldt4(sA4, M + (size_t)(i*64)*FF + j*64, tid);
    ldt4(sB4, M + (size_t)(kk*64)*FF + j*64, tid);
    __syncthreads();
    float acc[4][4] = {};
    g64_nt4(sA4, sB4, acc, ty, tx);
    #pragma unroll
    for (int ii = 0; ii < 4; ii++)
        #pragma unroll
        for (int j2 = 0; j2 < 4; j2++){
            size_t o = (size_t)(i*64 + ty*4 + ii)*FF + kk*64 + tx + 16*j2;
            M[o] -= acc[ii][j2];
        }
}

// -------------- Phase B (writes W fp32 + fp16 split) -------------
__global__ void __launch_bounds__(256) phaseB_k(){
    extern __shared__ float sm[];
    float* sA = sm;
    float* sC = sm + 2*64*PTW;
    float4* sA4 = (float4*)sA;
    float4* sB4 = (float4*)(sm + 64*PTW);
    float4* sC4 = (float4*)sC;
    int j   = blockIdx.x;
    int mat = blockIdx.y;
    float* M = g_M + (size_t)mat*FF*FF;
    float* W = g_W + (size_t)mat*FF*FF;
    uint32_t* wh = g_Wh + (size_t)mat*FF*(FF/2);
    int tid = threadIdx.x, tx = tid & 15, ty = tid >> 4;

    for (int i = j+1; i < 8; i++){
        float acc[4][4] = {};
        for (int k = j; k < i; k++){
            __syncthreads();
            ldt4(sA4, M + (size_t)(i*64)*FF + k*64, tid);
            ldt4(sB4, W + (size_t)(k*64)*FF + j*64, tid);
            __syncthreads();
            g64_nn4(sA4, sB4, acc, ty, tx);
        }
        __syncthreads();
        #pragma unroll
        for (int ii = 0; ii < 4; ii++){
            float4 v = {acc[ii][0], acc[ii][1], acc[ii][2], acc[ii][3]};
            sC4[(ty*4 + ii)*PT4 + tx] = v;
        }
        ldt4(sA4, W + (size_t)(i*64)*FF + i*64, tid);
        __syncthreads();
        float acc2[4][4] = {};
        g64_nn4(sA4, sC4, acc2, ty, tx);
        #pragma unroll
        for (int ii = 0; ii < 4; ii++){
            float v0 = -acc2[ii][0], v1 = -acc2[ii][1], v2 = -acc2[ii][2], v3 = -acc2[ii][3];
            float4 v = {v0, v1, v2, v3};
            size_t row = (size_t)(i*64 + ty*4 + ii);
            *(float4*)&W[row*FF + j*64 + 4*tx] = v;
            size_t o = row*(FF/2) + j*32 + 2*tx;
            wh[o]   = pack_h2(v0, v1);
            wh[o+1] = pack_h2(v2, v3);
        }
        __syncthreads();
    }
}

// ------------------------- queries -> fp16 pairs, transposed: [p][kp][q] -------------------------
__global__ void qsplit_k(const float* __restrict__ qf){
    __shared__ float sq[16][FF];
    int qb = blockIdx.x;           // 0..63 (16 queries each)
    int p  = blockIdx.y;
    int tid = threadIdx.x;
    for (int u = tid; u < 16*FF; u += 256){
        int qi = u / FF, f = u % FF;
        sq[qi][f] = qf[((size_t)p*QQ + qb*16 + qi)*FF + f];
    }
    __syncthreads();
    uint32_t* dh = g_Xh + (size_t)p*(FF/2)*QQ;
    for (int u = tid; u < 256*16; u += 256){
        int kp = u >> 4, qi = u & 15;
        dh[(size_t)kp*QQ + qb*16 + qi] = pack_h2(sq[qi][2*kp], sq[qi][2*kp+1]);
    }
}

// ------------------------- y = W * mu (fp32 exact, triangular) -------------------------
__global__ void ymu_k(){
    __shared__ float smu[FF];
    int pc = blockIdx.x;
    int tid = threadIdx.x, lane = tid & 31, wid = tid >> 5;
    const float* W = g_W + (size_t)pc*FF*FF;
    for (int f = tid; f < FF; f += 256) smu[f] = g_means[(size_t)pc*FF + f];
    __syncthreads();
    for (int r = wid; r < FF; r += 8){
        float s = 0.0f;
        for (int k = lane; k <= r; k += 32)
            s += W[(size_t)r*FF + k] * smu[k];
        #pragma unroll
        for (int o = 16; o; o >>= 1) s += __shfl_xor_sync(0xFFFFFFFFu, s, o);
        if (lane == 0) g_Ymu[pc*FF + r] = s;
    }
}

// ===== quad via single fp16 mma.sync, double-buffered: quad = || y - fp16(W)·fp16(x) ||^2 =====
// Grid (8 qtiles, 160 pc, 4 rb), 256 threads (8 warps: 2 m x 4 n), 2 CTAs/SM.
#define WPITCH 36
#define XPITCH 136
#define BUFU (128*WPITCH + 32*XPITCH)
#define QMMA_SMEM (2*BUFU*4 + 128*4)
__device__ __forceinline__ void stageWX(uint32_t* sW, uint32_t* sX,
                                        const uint4* gw, const uint4* gx,
                                        int rb, int kp0, int tid){
    #pragma unroll
    for (int u = tid; u < 1024; u += 256){
        int r = u >> 3, c4 = u & 7;
        *(uint4*)&sW[r*WPITCH + c4*4] = gw[(size_t)(rb*128 + r)*(FF/8) + (kp0 >> 2) + c4];
    }
    #pragma unroll
    for (int u = tid; u < 1024; u += 256){
        int kp = u >> 5, q4 = u & 31;
        *(uint4*)&sX[kp*XPITCH + q4*4] = gx[(size_t)(kp0 + kp)*(QQ/4) + q4];
    }
}
__global__ void __launch_bounds__(256, 2) quadmma_k(){
    extern __shared__ uint32_t smu32[];
    uint32_t* sW0 = smu32;
    uint32_t* sX0 = sW0 + 128*WPITCH;
    uint32_t* sW1 = smu32 + BUFU;
    uint32_t* sX1 = sW1 + 128*WPITCH;
    float*    red = (float*)(smu32 + 2*BUFU);
    int pc = blockIdx.y;
    int p = pc / CC, c = pc % CC;
    int qbase = blockIdx.x * 128;
    int rb = blockIdx.z;
    int tid = threadIdx.x, lane = tid & 31, wid = tid >> 5;
    int g = lane >> 2, t = lane & 3;
    int warpM = wid & 1, warpN = wid >> 1;
    int lm_row = (lane & 7) + ((lane >> 3) & 1)*8;
    int lm_col = (lane >> 4)*4;
    uint32_t sW0_b = smem_u32(sW0), sW1_b = smem_u32(sW1);
    const uint4* gwh4 = (const uint4*)(g_Wh + (size_t)pc*FF*(FF/2));
    const uint4* gxh4 = (const uint4*)(g_Xh + (size_t)p*(FF/2)*QQ + qbase);
    const float* ym = g_Ymu + pc*FF;

    if (tid < 128) red[tid] = 0.0f;
    float qs[8];
    #pragma unroll
    for (int j = 0; j < 8; j++) qs[j] = 0.0f;

    float acc[4][4][4];
    #pragma unroll
    for (int mi = 0; mi < 4; mi++)
        #pragma unroll
        for (int ni = 0; ni < 4; ni++)
            #pragma unroll
            for (int r = 0; r < 4; r++) acc[mi][ni][r] = 0.0f;

    int nch = 2*rb + 2;
    stageWX(sW0, sX0, gwh4, gxh4, rb, 0, tid);
    __syncthreads();
    for (int ch = 0; ch < nch; ch++){
        bool even = !(ch & 1);
        uint32_t* sX   = even ? sX0 : sX1;
        uint32_t  sW_b = even ? sW0_b : sW1_b;
        // prefetch next chunk into the other buffer (overlaps with MMAs below)
        if (ch + 1 < nch)
            stageWX(even ? sW1 : sW0, even ? sX1 : sX0, gwh4, gxh4, rb, (ch+1)*32, tid);

        bool diag = (ch >= 2*rb);
        int kbase = (ch - 2*rb)*64;
        #pragma unroll
        for (int s = 0; s < 4; s++){
            uint32_t bh[4][2];
            #pragma unroll
            for (int ni = 0; ni < 4; ni++){
                int col = warpN*32 + ni*8 + g;
                bh[ni][0] = sX[(8*s + t)*XPITCH + col];
                bh[ni][1] = sX[(8*s + t + 4)*XPITCH + col];
            }
            #pragma unroll
            for (int mi = 0; mi < 4; mi++){
                if (diag && (warpM*64 + mi*16 + 16 <= kbase + 16*s)) continue;
                uint32_t off = (uint32_t)(((warpM*64 + mi*16 + lm_row)*WPITCH + 8*s + lm_col)*4);
                uint32_t ah0,ah1,ah2,ah3;
                ldm4(ah0,ah1,ah2,ah3, sW_b + off);
                #pragma unroll
                for (int ni = 0; ni < 4; ni++)
                    MMA_F16(acc[mi][ni], ah0,ah1,ah2,ah3, bh[ni][0],bh[ni][1]);
            }
        }
        __syncthreads();
    }
    // epilogue: qs += (y - z)^2 over this CTA's 128 rows
    #pragma unroll
    for (int mi = 0; mi < 4; mi++){
        int r1 = rb*128 + warpM*64 + mi*16 + g;
        float y1 = ym[r1], y2 = ym[r1 + 8];
        #pragma unroll
        for (int ni = 0; ni < 4; ni++){
            float d0 = y1 - acc[mi][ni][0];
            float d1 = y1 - acc[mi][ni][1];
            float d2 = y2 - acc[mi][ni][2];
            float d3 = y2 - acc[mi][ni][3];
            qs[2*ni]   += d0*d0 + d2*d2;
            qs[2*ni+1] += d1*d1 + d3*d3;
        }
    }

    #pragma unroll
    for (int j = 0; j < 8; j++)
        #pragma unroll
        for (int o = 4; o < 32; o <<= 1)
            qs[j] += __shfl_xor_sync(0xFFFFFFFFu, qs[j], o);
    if (lane < 4){
        #pragma unroll
        for (int j = 0; j < 8; j++){
            int ni = j >> 1, b = j & 1;
            int q = warpN*32 + ni*8 + 2*lane + b;
            atomicAdd(&red[q], qs[j]);
        }
    }
    __syncthreads();
    if (tid < 128)
        atomicAdd(&g_quad[((size_t)p*QQ + qbase + tid)*CC + c], red[tid]);
}

// ------------------------- final outputs -------------------------
__global__ void logits_k(float* out){
    int q = blockIdx.x;
    int c = threadIdx.x;
    if (c < CC){
        float s = 0.0f;
        #pragma unroll
        for (int p = 0; p < PP; p++) s += g_quad[((size_t)p*QQ + q)*CC + c];
        out[q*CC + c] = -s * (1.0f/PP);
    }
}
__global__ void copymeans_k(float* out){
    for (int i = blockIdx.x*blockDim.x + threadIdx.x; i < NM*FF; i += gridDim.x*blockDim.x)
        out[QQ*CC + i] = g_means[i];
}

// ------------------------- launch -------------------------
extern "C" void kernel_launch(void* const* d_in, const int* in_sizes, int n_in,
                              void* d_out, int out_size) {
    const float* sf  = (const float*)d_in[0];
    const int*   lab = (const int*)d_in[1];
    const float* qf  = (const float*)d_in[2];
    float* out = (float*)d_out;

    const int CHOL_SMEM = 3*64*PTW*(int)sizeof(float);   // 52224
    const int TR_SMEM   = 2*64*PTW*(int)sizeof(float);   // 34816
    cudaFuncSetAttribute(diagpanel_k, cudaFuncAttributeMaxDynamicSharedMemorySize, CHOL_SMEM);
    cudaFuncSetAttribute(phaseB_k,    cudaFuncAttributeMaxDynamicSharedMemorySize, CHOL_SMEM);
    cudaFuncSetAttribute(quadmma_k,   cudaFuncAttributeMaxDynamicSharedMemorySize, QMMA_SMEM);

    setup_k<<<1, 32>>>(lab);
    means_k<<<NM, 256>>>(sf);
    tm_k<<<PP, 256>>>(sf);
    qsplit_k<<<dim3(64, PP), 256>>>(qf);
    taskcov_k<<<dim3(36, PP), 256>>>(sf);
    buildM_k<<<dim3(36, NM), 256>>>(sf);
    zeroWu_k<<<dim3(4, NM), 256>>>();
    zeroquad_k<<<160, 256>>>();
    for (int j = 0; j < 8; j++){
        diagpanel_k<<<NM, 256, CHOL_SMEM>>>(j);
        int nt = (7-j)*(8-j)/2;
        if (nt > 0)
            trailing_k<<<dim3(nt, NM), 256, TR_SMEM>>>(j);
    }
    phaseB_k<<<dim3(7, NM), 256, CHOL_SMEM>>>();
    ymu_k<<<NM, 256>>>();
    quadmma_k<<<dim3(8, NM, 4), 256, QMMA_SMEM>>>();
    logits_k<<<QQ, 32>>>(out);
    if (out_size >= QQ*CC + NM*FF)
        copymeans_k<<<160, 512>>>(out);
}

// round 13
// speedup vs baseline: 1.7558x; 1.1159x over previous
#include <cuda_runtime.h>
#include <cuda_fp16.h>
#include <math.h>
#include <stdint.h>

#define PP 8
#define TT 200
#define FF 512
#define CC 20
#define QQ 1024
#define NM (PP*CC)
typedef unsigned long long ULL;

// ------------------------- device scratch -------------------------
__device__ float g_means[NM*FF];
__device__ float g_tm[PP*FF];
__device__ float g_task[(size_t)PP*FF*FF];
__device__ float g_M[(size_t)NM*FF*FF];            // cov_reg -> L (in place)
__device__ float g_W[(size_t)NM*FF*FF];            // W = L^{-1} (fp32)
__device__ float g_quad[(size_t)PP*QQ*CC];
__device__ float g_Ymu[NM*FF];                     // y = W * mu (fp32 exact)
__device__ uint32_t g_Wh[(size_t)NM*FF*(FF/2)];    // fp16 pairs along k
__device__ uint32_t g_Xh[(size_t)PP*(FF/2)*QQ];    // [p][kp][q] fp16 pairs along k
__device__ int   g_members[CC*TT];
__device__ int   g_cnt[CC];
__device__ float g_icnts[CC], g_sclS[CC], g_sclT[CC];

// ------------------------- fp16 helpers -------------------------
__device__ __forceinline__ uint32_t pack_h2(float x0, float x1){
    __half h0 = __float2half_rn(x0);
    __half h1 = __float2half_rn(x1);
    return (uint32_t)__half_as_ushort(h0) | ((uint32_t)__half_as_ushort(h1) << 16);
}
__device__ __forceinline__ void split2f(float x0, float x1, uint32_t &hi, uint32_t &lo){
    __half h0 = __float2half_rn(x0);
    __half h1 = __float2half_rn(x1);
    float r0 = x0 - __half2float(h0);
    float r1 = x1 - __half2float(h1);
    __half l0 = __float2half_rn(r0);
    __half l1 = __float2half_rn(r1);
    hi = (uint32_t)__half_as_ushort(h0) | ((uint32_t)__half_as_ushort(h1) << 16);
    lo = (uint32_t)__half_as_ushort(l0) | ((uint32_t)__half_as_ushort(l1) << 16);
}

#define MMA_F16(c, a0,a1,a2,a3, b0,b1) \
    asm volatile("mma.sync.aligned.m16n8k16.row.col.f32.f16.f16.f32 " \
        "{%0,%1,%2,%3},{%4,%5,%6,%7},{%8,%9},{%0,%1,%2,%3};" \
        : "+f"(c[0]),"+f"(c[1]),"+f"(c[2]),"+f"(c[3]) \
        : "r"(a0),"r"(a1),"r"(a2),"r"(a3),"r"(b0),"r"(b1))

__device__ __forceinline__ void ldm4(uint32_t &r0, uint32_t &r1, uint32_t &r2, uint32_t &r3,
                                     uint32_t saddr){
    asm volatile("ldmatrix.sync.aligned.m8n8.x4.shared.b16 {%0,%1,%2,%3}, [%4];"
        : "=r"(r0), "=r"(r1), "=r"(r2), "=r"(r3) : "r"(saddr));
}
__device__ __forceinline__ uint32_t smem_u32(const void* p){
    uint32_t a;
    asm("{ .reg .u64 t; cvta.to.shared.u64 t, %1; cvt.u32.u64 %0, t; }" : "=r"(a) : "l"(p));
    return a;
}

// ------------------------- setup -------------------------
__global__ void setup_k(const int* __restrict__ lab_raw){
    if (threadIdx.x == 0 && blockIdx.x == 0){
        bool odd_all_zero = true;
        for (int t = 1; t < 200; t += 2) if (lab_raw[t] != 0) odd_all_zero = false;
        bool even_has_big = false;
        for (int t = 0; t < 200; t += 2) if (lab_raw[t] > 0) even_has_big = true;
        bool is64 = odd_all_zero && even_has_big;

        int cnt[CC];
        #pragma unroll
        for (int c = 0; c < CC; c++) cnt[c] = 0;
        for (int t = 0; t < TT; t++){
            int cc = is64 ? lab_raw[2*t] : lab_raw[t];
            if (cc < 0) cc = 0; if (cc >= CC) cc = CC-1;
            g_members[cc*TT + cnt[cc]] = t;
            cnt[cc]++;
        }
        for (int c = 0; c < CC; c++){
            g_cnt[c] = cnt[c];
            float cs  = fmaxf((float)cnt[c], 1.0f);
            g_icnts[c] = 1.0f / cs;
            float lam = cs / (cs + 1.0f);
            g_sclS[c] = lam / fmaxf((float)cnt[c] - 1.0f, 1.0f);
            g_sclT[c] = 1.0f - lam;
        }
    }
}

// ------------------------- class means -------------------------
__global__ void means_k(const float* __restrict__ sf){
    int pc = blockIdx.x;
    int p = pc / CC, c = pc % CC;
    int n = g_cnt[c];
    float ic = g_icnts[c];
    for (int f = threadIdx.x; f < FF; f += blockDim.x){
        float s = 0.0f;
        for (int m = 0; m < n; m++){
            int t = g_members[c*TT + m];
            s += sf[((size_t)p*TT + t)*FF + f];
        }
        g_means[(size_t)pc*FF + f] = s * ic;
    }
}

// ------------------------- task mean -------------------------
__global__ void tm_k(const float* __restrict__ sf){
    int p = blockIdx.x;
    for (int f = threadIdx.x; f < FF; f += blockDim.x){
        float s = 0.0f;
        for (int t = 0; t < TT; t++) s += sf[((size_t)p*TT + t)*FF + f];
        g_tm[p*FF + f] = s * (1.0f/TT);
    }
}

// ------------------------- task covariance -------------------------
__global__ void taskcov_k(const float* __restrict__ sf){
    int tile = blockIdx.x;          // 0..35 (tg<=tf)
    int p    = blockIdx.y;
    int tf = 0, rem = tile;
    while (rem >= tf+1){ rem -= tf+1; tf++; }
    int tg = rem;
    __shared__ float af[8][68], ag[8][68];
    int tid = threadIdx.x, tx = tid & 15, ty = tid >> 4;
    int r0 = ty*4, c0 = tx*4;
    float acc[4][4] = {};
    const float* tmv = g_tm + p*FF;
    for (int t0 = 0; t0 < TT; t0 += 8){
        __syncthreads();
        #pragma unroll
        for (int ii = 0; ii < 2; ii++){
            int idx = ii*256 + tid;
            int s = idx >> 6, f = idx & 63;
            const float* row = sf + ((size_t)p*TT + t0 + s)*FF;
            af[s][f] = row[tf*64 + f] - tmv[tf*64 + f];
            ag[s][f] = row[tg*64 + f] - tmv[tg*64 + f];
        }
        __syncthreads();
        #pragma unroll
        for (int s = 0; s < 8; s++){
            float a[4], b[4];
            #pragma unroll
            for (int i = 0; i < 4; i++) a[i] = af[s][r0+i];
            #pragma unroll
            for (int j = 0; j < 4; j++) b[j] = ag[s][c0+j];
            #pragma unroll
            for (int i = 0; i < 4; i++)
                #pragma unroll
                for (int j = 0; j < 4; j++) acc[i][j] += a[i]*b[j];
        }
    }
    const float inv = 1.0f/(TT-1);
    float* dst = g_task + (size_t)p*FF*FF;
    #pragma unroll
    for (int i = 0; i < 4; i++)
        #pragma unroll
        for (int j = 0; j < 4; j++){
            int fr = tf*64 + r0 + i, gc = tg*64 + c0 + j;
            float v = acc[i][j]*inv;
            dst[(size_t)fr*FF + gc] = v;
            dst[(size_t)gc*FF + fr] = v;
        }
}

// ------------------------- cov_reg -------------------------
__global__ void buildM_k(const float* __restrict__ sf){
    int tile = blockIdx.x;          // 0..35
    int pc   = blockIdx.y;
    int p = pc / CC, c = pc % CC;
    int tf = 0, rem = tile;
    while (rem >= tf+1){ rem -= tf+1; tf++; }
    int tg = rem;
    __shared__ float af[4][68], ag[4][68];
    int tid = threadIdx.x, tx = tid & 15, ty = tid >> 4;
    int r0 = ty*4, c0 = tx*4;
    float acc[4][4] = {};
    int n = g_cnt[c];
    const float* mu = g_means + (size_t)pc*FF;
    for (int m0 = 0; m0 < n; m0 += 4){
        __syncthreads();
        {
            int s = tid >> 6, f = tid & 63;
            int m = m0 + s;
            float va = 0.0f, vg = 0.0f;
            if (m < n){
                int t = g_members[c*TT + m];
                const float* row = sf + ((size_t)p*TT + t)*FF;
                va = row[tf*64 + f] - mu[tf*64 + f];
                vg = row[tg*64 + f] - mu[tg*64 + f];
            }
            af[s][f] = va; ag[s][f] = vg;
        }
        __syncthreads();
        #pragma unroll
        for (int s = 0; s < 4; s++){
            float a[4], b[4];
            #pragma unroll
            for (int i = 0; i < 4; i++) a[i] = af[s][r0+i];
            #pragma unroll
            for (int j = 0; j < 4; j++) b[j] = ag[s][c0+j];
            #pragma unroll
            for (int i = 0; i < 4; i++)
                #pragma unroll
                for (int j = 0; j < 4; j++) acc[i][j] += a[i]*b[j];
        }
    }
    float ss = g_sclS[c], st = g_sclT[c];
    float* dst = g_M + (size_t)pc*FF*FF;
    const float* tk = g_task + (size_t)p*FF*FF;
    #pragma unroll
    for (int i = 0; i < 4; i++)
        #pragma unroll
        for (int j = 0; j < 4; j++){
            int fr = tf*64 + r0 + i, gc = tg*64 + c0 + j;
            float v = ss*acc[i][j] + st*tk[(size_t)fr*FF + gc] + ((fr == gc) ? 1.0f : 0.0f);
            dst[(size_t)fr*FF + gc] = v;
            dst[(size_t)gc*FF + fr] = v;
        }
}

// -------- zero Wh in the upper-right 64x64 of each 128-diag block --------
__global__ void zeroWu_k(){
    int rb  = blockIdx.x;
    int mat = blockIdx.y;
    uint32_t* wh = g_Wh + (size_t)mat*FF*(FF/2);
    for (int e = threadIdx.x; e < 64*32; e += 256){
        int r = e >> 5, cp = e & 31;
        size_t o = (size_t)(rb*128 + r)*(FF/2) + rb*64 + 32 + cp;
        wh[o] = 0u;
    }
}

// -------- zero g_quad --------
__global__ void zeroquad_k(){
    size_t n = (size_t)PP*QQ*CC;
    for (size_t i = (size_t)blockIdx.x*blockDim.x + threadIdx.x; i < n;
         i += (size_t)gridDim.x*blockDim.x)
        g_quad[i] = 0.0f;
}

// ================== fp16 3-term 64x64x64 tile GEMM machinery ==================
// Arrays: [64 rows][32 kp] u32 pairs-along-k, pitch WP=36 (16B-aligned rows, cf-free ldmatrix)
#define WP 36
// stage + split a k-contiguous 64x64 fp32 global tile
__device__ __forceinline__ void stg_split(uint32_t* dh, uint32_t* dl,
                                          const float* g, int tid){
    #pragma unroll
    for (int e = tid; e < 2048; e += 256){
        int r = e >> 5, kp = e & 31;
        float2 v = *(const float2*)&g[(size_t)r*FF + 2*kp];
        uint32_t hi, lo; split2f(v.x, v.y, hi, lo);
        dh[r*WP + kp] = hi; dl[r*WP + kp] = lo;
    }
}
// stage + split the TRANSPOSE of a 64x64 fp32 global tile (dst[n][kp] = src[2kp..][n])
__device__ __forceinline__ void stg_splitT(uint32_t* dh, uint32_t* dl,
                                           const float* g, int tid){
    #pragma unroll
    for (int e = tid; e < 2048; e += 256){
        int n = e & 63, kp = e >> 6;
        float x0 = g[(size_t)(2*kp)*FF + n];
        float x1 = g[(size_t)(2*kp+1)*FF + n];
        uint32_t hi, lo; split2f(x0, x1, hi, lo);
        dh[n*WP + kp] = hi; dl[n*WP + kp] = lo;
    }
}
// same, but source is shared fp32 with pitch 65
__device__ __forceinline__ void stg_splitT_s(uint32_t* dh, uint32_t* dl,
                                             const float* s, int tid){
    #pragma unroll
    for (int e = tid; e < 2048; e += 256){
        int n = e & 63, kp = e >> 6;
        uint32_t hi, lo; split2f(s[(2*kp)*65 + n], s[(2*kp+1)*65 + n], hi, lo);
        dh[n*WP + kp] = hi; dl[n*WP + kp] = lo;
    }
}
// C(16x32 per warp) += A * B^T, 3-term fp16. warpM in 0..3, warpN in 0..1.
__device__ __forceinline__ void h64nt3(uint32_t sAh_b, uint32_t sAl_b,
                                       uint32_t sBh_b, uint32_t sBl_b,
                                       float acc[4][4], int warpM, int warpN,
                                       int lm_row, int lm_col){
    #pragma unroll
    for (int s = 0; s < 4; s++){
        uint32_t aoff = (uint32_t)(((warpM*16 + lm_row)*WP + 8*s + lm_col)*4);
        uint32_t ah0,ah1,ah2,ah3, al0,al1,al2,al3;
        ldm4(ah0,ah1,ah2,ah3, sAh_b + aoff);
        ldm4(al0,al1,al2,al3, sAl_b + aoff);
        #pragma unroll
        for (int bn = 0; bn < 2; bn++){
            uint32_t boff = (uint32_t)(((warpN*32 + bn*16 + lm_row)*WP + 8*s + lm_col)*4);
            uint32_t bh0,bh1,bh2,bh3, bl0,bl1,bl2,bl3;
            ldm4(bh0,bh1,bh2,bh3, sBh_b + boff);
            ldm4(bl0,bl1,bl2,bl3, sBl_b + boff);
            MMA_F16(acc[bn*2],   ah0,ah1,ah2,ah3, bh0,bh2);
            MMA_F16(acc[bn*2],   ah0,ah1,ah2,ah3, bl0,bl2);
            MMA_F16(acc[bn*2],   al0,al1,al2,al3, bh0,bh2);
            MMA_F16(acc[bn*2+1], ah0,ah1,ah2,ah3, bh1,bh3);
            MMA_F16(acc[bn*2+1], ah0,ah1,ah2,ah3, bl1,bl3);
            MMA_F16(acc[bn*2+1], al0,al1,al2,al3, bh1,bh3);
        }
    }
}

// ------------- 64x64 float4 tile helpers for diagpanel (pitch 17 float4) -------------
#define PTW 68
#define PT4 17
__device__ __forceinline__ void ldt4(float4* dst, const float* g, int tid){
    #pragma unroll
    for (int e = tid; e < 1024; e += 256){
        int r = e >> 4, c4 = e & 15;
        dst[r*PT4 + c4] = *(const float4*)&g[(size_t)r*FF + c4*4];
    }
}
__device__ __forceinline__ float dot4(float4 a, float4 b){
    return a.x*b.x + a.y*b.y + a.z*b.z + a.w*b.w;
}
__device__ __forceinline__ void g64_nt4(const float4* A, const float4* B,
                                        float acc[4][4], int ty, int tx){
    #pragma unroll 4
    for (int kq = 0; kq < 16; kq++){
        float4 a[4], b[4];
        #pragma unroll
        for (int i = 0; i < 4; i++) a[i] = A[(ty*4+i)*PT4 + kq];
        #pragma unroll
        for (int j = 0; j < 4; j++) b[j] = B[(tx+16*j)*PT4 + kq];
        #pragma unroll
        for (int i = 0; i < 4; i++)
            #pragma unroll
            for (int j = 0; j < 4; j++) acc[i][j] += dot4(a[i], b[j]);
    }
}

// -------------- Phase A step j: diag factor + tri-inverse + panel (fp32) --------
__global__ void __launch_bounds__(256) diagpanel_k(int j){
    extern __shared__ float sm[];
    float* sA = sm;                 // 64*68 words
    float* sB = sm + 64*PTW;
    float* sC = sm + 2*64*PTW;
    float4* sB4 = (float4*)sB;
    float4* sC4 = (float4*)sC;
    int mat = blockIdx.x;
    float* M = g_M + (size_t)mat*FF*FF;
    float* W = g_W + (size_t)mat*FF*FF;
    int tid = threadIdx.x, tx = tid & 15, ty = tid >> 4;

    ldt4((float4*)sA, M + (size_t)(j*64)*FF + j*64, tid);
    __syncthreads();
    for (int k = 0; k < 64; k++){
        float pinv = 1.0f / sA[k*PTW+k];
        #pragma unroll 4
        for (int e = tid; e < 4096; e += 256){
            int r = e >> 6, cc = e & 63;
            if (r > k && cc > k && cc <= r)
                sA[r*PTW+cc] -= sA[r*PTW+k]*sA[cc*PTW+k]*pinv;
        }
        __syncthreads();
    }
    if (tid < 64) sC[tid] = rsqrtf(sA[tid*PTW+tid]);
    __syncthreads();
    #pragma unroll 4
    for (int e = tid; e < 4096; e += 256){
        int r = e >> 6, cc = e & 63;
        if (cc <= r) sA[r*PTW+cc] *= sC[cc];
    }
    __syncthreads();

    #pragma unroll 4
    for (int e = tid; e < 4096; e += 256) sB[(e>>6)*PTW + (e&63)] = 0.0f;
    __syncthreads();
    {
        int c = tid >> 2, s = tid & 3;
        unsigned gmask = 0xFu << ((tid & 31) & ~3);
        float dv = 1.0f / sA[c*PTW+c];
        if (s == 0) sB[c*PTW+c] = dv;
        __syncwarp(gmask);
        for (int r = c+1; r < 64; r++){
            float part = 0.0f;
            for (int k2 = c + s; k2 < r; k2 += 4)
                part += sA[r*PTW+k2] * sB[k2*PTW+c];
            part += __shfl_xor_sync(gmask, part, 1);
            part += __shfl_xor_sync(gmask, part, 2);
            if (s == 0) sB[r*PTW+c] = -part / sA[r*PTW+r];
            __syncwarp(gmask);
        }
    }
    __syncthreads();
    #pragma unroll 4
    for (int e = tid; e < 4096; e += 256){
        int r = e >> 6, cc = e & 63;
        W[(size_t)(j*64 + r)*FF + j*64 + cc] = sB[r*PTW+cc];
    }
    {
        uint32_t* wh = g_Wh + (size_t)mat*FF*(FF/2);
        for (int e = tid; e < 2048; e += 256){
            int r = e >> 5, cp = e & 31;
            size_t o = (size_t)(j*64 + r)*(FF/2) + j*32 + cp;
            wh[o] = pack_h2(sB[r*PTW + 2*cp], sB[r*PTW + 2*cp + 1]);
        }
    }
    for (int i = j+1; i < 8; i++){
        __syncthreads();
        ldt4(sC4, M + (size_t)(i*64)*FF + j*64, tid);
        __syncthreads();
        float acc[4][4] = {};
        g64_nt4(sC4, sB4, acc, ty, tx);
        #pragma unroll
        for (int ii = 0; ii < 4; ii++)
            #pragma unroll
            for (int j2 = 0; j2 < 4; j2++)
                M[(size_t)(i*64 + ty*4 + ii)*FF + j*64 + tx + 16*j2] = acc[ii][j2];
    }
}

// -------------- Phase A trailing: fp16 3-term MMA -------------
#define TR_SMEM (4*64*WP*4)
__global__ void __launch_bounds__(256) trailing_k(int j){
    extern __shared__ uint32_t su[];
    uint32_t* sAh = su;
    uint32_t* sAl = sAh + 64*WP;
    uint32_t* sBh = sAl + 64*WP;
    uint32_t* sBl = sBh + 64*WP;
    int mat = blockIdx.y;
    int t = blockIdx.x;
    int i = j+1, cnt = 1;
    while (t >= cnt){ t -= cnt; i++; cnt = i - j; }
    int kk = j+1 + t;
    float* M = g_M + (size_t)mat*FF*FF;
    int tid = threadIdx.x, lane = tid & 31, wid = tid >> 5;
    int g = lane >> 2, tt = lane & 3;
    int warpM = wid & 3, warpN = wid >> 2;
    int lm_row = (lane & 7) + ((lane >> 3) & 1)*8;
    int lm_col = (lane >> 4)*4;

    stg_split(sAh, sAl, M + (size_t)(i*64)*FF + j*64, tid);
    stg_split(sBh, sBl, M + (size_t)(kk*64)*FF + j*64, tid);
    __syncthreads();
    float acc[4][4] = {};
    h64nt3(smem_u32(sAh), smem_u32(sAl), smem_u32(sBh), smem_u32(sBl),
           acc, warpM, warpN, lm_row, lm_col);
    // write back: M[i-rows][kk-cols] -= acc
    #pragma unroll
    for (int ni = 0; ni < 4; ni++){
        int cbase = kk*64 + warpN*32 + ni*8 + 2*tt;
        int r0 = i*64 + warpM*16 + g;
        float2* p0 = (float2*)&M[(size_t)r0*FF + cbase];
        float2 v0 = *p0; v0.x -= acc[ni][0]; v0.y -= acc[ni][1]; *p0 = v0;
        float2* p1 = (float2*)&M[(size_t)(r0+8)*FF + cbase];
        float2 v1 = *p1; v1.x -= acc[ni][2]; v1.y -= acc[ni][3]; *p1 = v1;
    }
}

// -------------- Phase B: fp16 3-term MMA (NN via transpose staging) -------------
#define PB_SMEM (4*64*WP*4 + 64*65*4)
__global__ void __launch_bounds__(256) phaseB_k(){
    extern __shared__ uint32_t su[];
    uint32_t* sAh = su;
    uint32_t* sAl = sAh + 64*WP;
    uint32_t* sBh = sAl + 64*WP;
    uint32_t* sBl = sBh + 64*WP;
    float*    sC  = (float*)(sBl + 64*WP);      // 64x65 fp32
    int j   = blockIdx.x;
    int mat = blockIdx.y;
    float* M = g_M + (size_t)mat*FF*FF;
    float* W = g_W + (size_t)mat*FF*FF;
    uint32_t* wh = g_Wh + (size_t)mat*FF*(FF/2);
    int tid = threadIdx.x, lane = tid & 31, wid = tid >> 5;
    int g = lane >> 2, tt = lane & 3;
    int warpM = wid & 3, warpN = wid >> 2;
    int lm_row = (lane & 7) + ((lane >> 3) & 1)*8;
    int lm_col = (lane >> 4)*4;
    uint32_t sAh_b = smem_u32(sAh), sAl_b = smem_u32(sAl);
    uint32_t sBh_b = smem_u32(sBh), sBl_b = smem_u32(sBl);

    for (int i = j+1; i < 8; i++){
        float acc[4][4] = {};
        for (int k = j; k < i; k++){
            __syncthreads();
            stg_split (sAh, sAl, M + (size_t)(i*64)*FF + k*64, tid);   // L_ik
            stg_splitT(sBh, sBl, W + (size_t)(k*64)*FF + j*64, tid);   // W_kj^T
            __syncthreads();
            h64nt3(sAh_b, sAl_b, sBh_b, sBl_b, acc, warpM, warpN, lm_row, lm_col);
        }
        __syncthreads();
        // S -> sC (fp32, pitch 65)
        #pragma unroll
        for (int ni = 0; ni < 4; ni++){
            int cbase = warpN*32 + ni*8 + 2*tt;
            int r0 = warpM*16 + g;
            sC[r0*65 + cbase]     = acc[ni][0];
            sC[r0*65 + cbase + 1] = acc[ni][1];
            sC[(r0+8)*65 + cbase]     = acc[ni][2];
            sC[(r0+8)*65 + cbase + 1] = acc[ni][3];
        }
        __syncthreads();
        stg_split  (sAh, sAl, W + (size_t)(i*64)*FF + i*64, tid);      // Linv_ii
        stg_splitT_s(sBh, sBl, sC, tid);                               // S^T
        __syncthreads();
        float acc2[4][4] = {};
        h64nt3(sAh_b, sAl_b, sBh_b, sBl_b, acc2, warpM, warpN, lm_row, lm_col);
        // W_ij = -acc2 (fp32 + fp16 pack)
        #pragma unroll
        for (int ni = 0; ni < 4; ni++){
            int cbase = warpN*32 + ni*8 + 2*tt;
            #pragma unroll
            for (int h = 0; h < 2; h++){
                int row = i*64 + warpM*16 + g + h*8;
                float v0 = -acc2[ni][h*2], v1 = -acc2[ni][h*2+1];
                float2 v = {v0, v1};
                *(float2*)&W[(size_t)row*FF + j*64 + cbase] = v;
                wh[(size_t)row*(FF/2) + j*32 + (cbase >> 1)] = pack_h2(v0, v1);
            }
        }
        __syncthreads();
    }
}

// ------------------------- queries -> fp16 pairs, transposed -------------------------
__global__ void qsplit_k(const float* __restrict__ qf){
    __shared__ float sq[16][FF];
    int qb = blockIdx.x;
    int p  = blockIdx.y;
    int tid = threadIdx.x;
    for (int u = tid; u < 16*FF; u += 256){
        int qi = u / FF, f = u % FF;
        sq[qi][f] = qf[((size_t)p*QQ + qb*16 + qi)*FF + f];
    }
    __syncthreads();
    uint32_t* dh = g_Xh + (size_t)p*(FF/2)*QQ;
    for (int u = tid; u < 256*16; u += 256){
        int kp = u >> 4, qi = u & 15;
        dh[(size_t)kp*QQ + qb*16 + qi] = pack_h2(sq[qi][2*kp], sq[qi][2*kp+1]);
    }
}

// ------------------------- y = W * mu (fp32 exact, triangular) -------------------------
__global__ void ymu_k(){
    __shared__ float smu[FF];
    int pc = blockIdx.x;
    int tid = threadIdx.x, lane = tid & 31, wid = tid >> 5;
    const float* W = g_W + (size_t)pc*FF*FF;
    for (int f = tid; f < FF; f += 256) smu[f] = g_means[(size_t)pc*FF + f];
    __syncthreads();
    for (int r = wid; r < FF; r += 8){
        float s = 0.0f;
        for (int k = lane; k <= r; k += 32)
            s += W[(size_t)r*FF + k] * smu[k];
        #pragma unroll
        for (int o = 16; o; o >>= 1) s += __shfl_xor_sync(0xFFFFFFFFu, s, o);
        if (lane == 0) g_Ymu[pc*FF + r] = s;
    }
}

// ===== quad via single fp16 mma.sync, double-buffered =====
#define WPITCH 36
#define XPITCH 136
#define BUFU (128*WPITCH + 32*XPITCH)
#define QMMA_SMEM (2*BUFU*4 + 128*4)
__device__ __forceinline__ void stageWX(uint32_t* sW, uint32_t* sX,
                                        const uint4* gw, const uint4* gx,
                                        int rb, int kp0, int tid){
    #pragma unroll
    for (int u = tid; u < 1024; u += 256){
        int r = u >> 3, c4 = u & 7;
        *(uint4*)&sW[r*WPITCH + c4*4] = gw[(size_t)(rb*128 + r)*(FF/8) + (kp0 >> 2) + c4];
    }
    #pragma unroll
    for (int u = tid; u < 1024; u += 256){
        int kp = u >> 5, q4 = u & 31;
        *(uint4*)&sX[kp*XPITCH + q4*4] = gx[(size_t)(kp0 + kp)*(QQ/4) + q4];
    }
}
__global__ void __launch_bounds__(256, 2) quadmma_k(){
    extern __shared__ uint32_t smu32[];
    uint32_t* sW0 = smu32;
    uint32_t* sX0 = sW0 + 128*WPITCH;
    uint32_t* sW1 = smu32 + BUFU;
    uint32_t* sX1 = sW1 + 128*WPITCH;
    float*    red = (float*)(smu32 + 2*BUFU);
    int pc = blockIdx.y;
    int p = pc / CC, c = pc % CC;
    int qbase = blockIdx.x * 128;
    int rb = blockIdx.z;
    int tid = threadIdx.x, lane = tid & 31, wid = tid >> 5;
    int g = lane >> 2, t = lane & 3;
    int warpM = wid & 1, warpN = wid >> 1;
    int lm_row = (lane & 7) + ((lane >> 3) & 1)*8;
    int lm_col = (lane >> 4)*4;
    uint32_t sW0_b = smem_u32(sW0), sW1_b = smem_u32(sW1);
    const uint4* gwh4 = (const uint4*)(g_Wh + (size_t)pc*FF*(FF/2));
    const uint4* gxh4 = (const uint4*)(g_Xh + (size_t)p*(FF/2)*QQ + qbase);
    const float* ym = g_Ymu + pc*FF;

    if (tid < 128) red[tid] = 0.0f;
    float qs[8];
    #pragma unroll
    for (int j = 0; j < 8; j++) qs[j] = 0.0f;

    float acc[4][4][4];
    #pragma unroll
    for (int mi = 0; mi < 4; mi++)
        #pragma unroll
        for (int ni = 0; ni < 4; ni++)
            #pragma unroll
            for (int r = 0; r < 4; r++) acc[mi][ni][r] = 0.0f;

    int nch = 2*rb + 2;
    stageWX(sW0, sX0, gwh4, gxh4, rb, 0, tid);
    __syncthreads();
    for (int ch = 0; ch < nch; ch++){
        bool even = !(ch & 1);
        uint32_t* sX   = even ? sX0 : sX1;
        uint32_t  sW_b = even ? sW0_b : sW1_b;
        if (ch + 1 < nch)
            stageWX(even ? sW1 : sW0, even ? sX1 : sX0, gwh4, gxh4, rb, (ch+1)*32, tid);

        bool diag = (ch >= 2*rb);
        int kbase = (ch - 2*rb)*64;
        #pragma unroll
        for (int s = 0; s < 4; s++){
            uint32_t bh[4][2];
            #pragma unroll
            for (int ni = 0; ni < 4; ni++){
                int col = warpN*32 + ni*8 + g;
                bh[ni][0] = sX[(8*s + t)*XPITCH + col];
                bh[ni][1] = sX[(8*s + t + 4)*XPITCH + col];
            }
            #pragma unroll
            for (int mi = 0; mi < 4; mi++){
                if (diag && (warpM*64 + mi*16 + 16 <= kbase + 16*s)) continue;
                uint32_t off = (uint32_t)(((warpM*64 + mi*16 + lm_row)*WPITCH + 8*s + lm_col)*4);
                uint32_t ah0,ah1,ah2,ah3;
                ldm4(ah0,ah1,ah2,ah3, sW_b + off);
                #pragma unroll
                for (int ni = 0; ni < 4; ni++)
                    MMA_F16(acc[mi][ni], ah0,ah1,ah2,ah3, bh[ni][0],bh[ni][1]);
            }
        }
        __syncthreads();
    }
    #pragma unroll
    for (int mi = 0; mi < 4; mi++){
        int r1 = rb*128 + warpM*64 + mi*16 + g;
        float y1 = ym[r1], y2 = ym[r1 + 8];
        #pragma unroll
        for (int ni = 0; ni < 4; ni++){
            float d0 = y1 - acc[mi][ni][0];
            float d1 = y1 - acc[mi][ni][1];
            float d2 = y2 - acc[mi][ni][2];
            float d3 = y2 - acc[mi][ni][3];
            qs[2*ni]   += d0*d0 + d2*d2;
            qs[2*ni+1] += d1*d1 + d3*d3;
        }
    }
    #pragma unroll
    for (int j = 0; j < 8; j++)
        #pragma unroll
        for (int o = 4; o < 32; o <<= 1)
            qs[j] += __shfl_xor_sync(0xFFFFFFFFu, qs[j], o);
    if (lane < 4){
        #pragma unroll
        for (int j = 0; j < 8; j++){
            int ni = j >> 1, b = j & 1;
            int q = warpN*32 + ni*8 + 2*lane + b;
            atomicAdd(&red[q], qs[j]);
        }
    }
    __syncthreads();
    if (tid < 128)
        atomicAdd(&g_quad[((size_t)p*QQ + qbase + tid)*CC + c], red[tid]);
}

// ------------------------- final outputs -------------------------
__global__ void logits_k(float* out){
    int q = blockIdx.x;
    int c = threadIdx.x;
    if (c < CC){
        float s = 0.0f;
        #pragma unroll
        for (int p = 0; p < PP; p++) s += g_quad[((size_t)p*QQ + q)*CC + c];
        out[q*CC + c] = -s * (1.0f/PP);
    }
}
__global__ void copymeans_k(float* out){
    for (int i = blockIdx.x*blockDim.x + threadIdx.x; i < NM*FF; i += gridDim.x*blockDim.x)
        out[QQ*CC + i] = g_means[i];
}

// ------------------------- launch -------------------------
extern "C" void kernel_launch(void* const* d_in, const int* in_sizes, int n_in,
                              void* d_out, int out_size) {
    const float* sf  = (const float*)d_in[0];
    const int*   lab = (const int*)d_in[1];
    const float* qf  = (const float*)d_in[2];
    float* out = (float*)d_out;

    const int CHOL_SMEM = 3*64*PTW*(int)sizeof(float);   // 52224
    cudaFuncSetAttribute(diagpanel_k, cudaFuncAttributeMaxDynamicSharedMemorySize, CHOL_SMEM);
    cudaFuncSetAttribute(phaseB_k,    cudaFuncAttributeMaxDynamicSharedMemorySize, PB_SMEM);
    cudaFuncSetAttribute(trailing_k,  cudaFuncAttributeMaxDynamicSharedMemorySize, TR_SMEM);
    cudaFuncSetAttribute(quadmma_k,   cudaFuncAttributeMaxDynamicSharedMemorySize, QMMA_SMEM);

    setup_k<<<1, 32>>>(lab);
    means_k<<<NM, 256>>>(sf);
    tm_k<<<PP, 256>>>(sf);
    qsplit_k<<<dim3(64, PP), 256>>>(qf);
    taskcov_k<<<dim3(36, PP), 256>>>(sf);
    buildM_k<<<dim3(36, NM), 256>>>(sf);
    zeroWu_k<<<dim3(4, NM), 256>>>();
    zeroquad_k<<<160, 256>>>();
    for (int j = 0; j < 8; j++){
        diagpanel_k<<<NM, 256, CHOL_SMEM>>>(j);
        int nt = (7-j)*(8-j)/2;
        if (nt > 0)
            trailing_k<<<dim3(nt, NM), 256, TR_SMEM>>>(j);
    }
    phaseB_k<<<dim3(7, NM), 256, PB_SMEM>>>();
    ymu_k<<<NM, 256>>>();
    quadmma_k<<<dim3(8, NM, 4), 256, QMMA_SMEM>>>();
    logits_k<<<QQ, 32>>>(out);
    if (out_size >= QQ*CC + NM*FF)
        copymeans_k<<<160, 512>>>(out);
}

// round 17
// speedup vs baseline: 1.7692x; 1.0076x over previous
#include <cuda_runtime.h>
#include <cuda_fp16.h>
#include <math.h>
#include <stdint.h>

#define PP 8
#define TT 200
#define FF 512
#define CC 20
#define QQ 1024
#define NM (PP*CC)
typedef unsigned long long ULL;

// ------------------------- device scratch -------------------------
__device__ float g_means[NM*FF];
__device__ float g_tm[PP*FF];
__device__ float g_task[(size_t)PP*FF*FF];
__device__ float g_M[(size_t)NM*FF*FF];            // cov_reg -> L (in place)
__device__ float g_W[(size_t)NM*FF*FF];            // W = L^{-1} (fp32)
__device__ float g_quad[(size_t)PP*QQ*CC];
__device__ float g_Ymu[NM*FF];                     // y = W * mu (fp32 exact)
__device__ uint32_t g_Wh[(size_t)NM*FF*(FF/2)];    // fp16 pairs along k
__device__ uint32_t g_Xh[(size_t)PP*(FF/2)*QQ];    // [p][kp][q] fp16 pairs along k
__device__ int   g_members[CC*TT];
__device__ int   g_cnt[CC];
__device__ float g_icnts[CC], g_sclS[CC], g_sclT[CC];

// ------------------------- fp16 helpers -------------------------
__device__ __forceinline__ uint32_t pack_h2(float x0, float x1){
    __half h0 = __float2half_rn(x0);
    __half h1 = __float2half_rn(x1);
    return (uint32_t)__half_as_ushort(h0) | ((uint32_t)__half_as_ushort(h1) << 16);
}
__device__ __forceinline__ void split2f(float x0, float x1, uint32_t &hi, uint32_t &lo){
    __half h0 = __float2half_rn(x0);
    __half h1 = __float2half_rn(x1);
    float r0 = x0 - __half2float(h0);
    float r1 = x1 - __half2float(h1);
    __half l0 = __float2half_rn(r0);
    __half l1 = __float2half_rn(r1);
    hi = (uint32_t)__half_as_ushort(h0) | ((uint32_t)__half_as_ushort(h1) << 16);
    lo = (uint32_t)__half_as_ushort(l0) | ((uint32_t)__half_as_ushort(l1) << 16);
}

#define MMA_F16(c, a0,a1,a2,a3, b0,b1) \
    asm volatile("mma.sync.aligned.m16n8k16.row.col.f32.f16.f16.f32 " \
        "{%0,%1,%2,%3},{%4,%5,%6,%7},{%8,%9},{%0,%1,%2,%3};" \
        : "+f"(c[0]),"+f"(c[1]),"+f"(c[2]),"+f"(c[3]) \
        : "r"(a0),"r"(a1),"r"(a2),"r"(a3),"r"(b0),"r"(b1))

__device__ __forceinline__ void ldm4(uint32_t &r0, uint32_t &r1, uint32_t &r2, uint32_t &r3,
                                     uint32_t saddr){
    asm volatile("ldmatrix.sync.aligned.m8n8.x4.shared.b16 {%0,%1,%2,%3}, [%4];"
        : "=r"(r0), "=r"(r1), "=r"(r2), "=r"(r3) : "r"(saddr));
}
__device__ __forceinline__ uint32_t smem_u32(const void* p){
    uint32_t a;
    asm("{ .reg .u64 t; cvta.to.shared.u64 t, %1; cvt.u32.u64 %0, t; }" : "=r"(a) : "l"(p));
    return a;
}

// ------------------------- setup -------------------------
__global__ void setup_k(const int* __restrict__ lab_raw){
    if (threadIdx.x == 0 && blockIdx.x == 0){
        bool odd_all_zero = true;
        for (int t = 1; t < 200; t += 2) if (lab_raw[t] != 0) odd_all_zero = false;
        bool even_has_big = false;
        for (int t = 0; t < 200; t += 2) if (lab_raw[t] > 0) even_has_big = true;
        bool is64 = odd_all_zero && even_has_big;

        int cnt[CC];
        #pragma unroll
        for (int c = 0; c < CC; c++) cnt[c] = 0;
        for (int t = 0; t < TT; t++){
            int cc = is64 ? lab_raw[2*t] : lab_raw[t];
            if (cc < 0) cc = 0; if (cc >= CC) cc = CC-1;
            g_members[cc*TT + cnt[cc]] = t;
            cnt[cc]++;
        }
        for (int c = 0; c < CC; c++){
            g_cnt[c] = cnt[c];
            float cs  = fmaxf((float)cnt[c], 1.0f);
            g_icnts[c] = 1.0f / cs;
            float lam = cs / (cs + 1.0f);
            g_sclS[c] = lam / fmaxf((float)cnt[c] - 1.0f, 1.0f);
            g_sclT[c] = 1.0f - lam;
        }
    }
}

// ------------------------- class means -------------------------
__global__ void means_k(const float* __restrict__ sf){
    int pc = blockIdx.x;
    int p = pc / CC, c = pc % CC;
    int n = g_cnt[c];
    float ic = g_icnts[c];
    for (int f = threadIdx.x; f < FF; f += blockDim.x){
        float s = 0.0f;
        for (int m = 0; m < n; m++){
            int t = g_members[c*TT + m];
            s += sf[((size_t)p*TT + t)*FF + f];
        }
        g_means[(size_t)pc*FF + f] = s * ic;
    }
}

// ------------------------- task mean -------------------------
__global__ void tm_k(const float* __restrict__ sf){
    int p = blockIdx.x;
    for (int f = threadIdx.x; f < FF; f += blockDim.x){
        float s = 0.0f;
        for (int t = 0; t < TT; t++) s += sf[((size_t)p*TT + t)*FF + f];
        g_tm[p*FF + f] = s * (1.0f/TT);
    }
}

// ------------------------- task covariance -------------------------
__global__ void taskcov_k(const float* __restrict__ sf){
    int tile = blockIdx.x;          // 0..35 (tg<=tf)
    int p    = blockIdx.y;
    int tf = 0, rem = tile;
    while (rem >= tf+1){ rem -= tf+1; tf++; }
    int tg = rem;
    __shared__ float af[8][68], ag[8][68];
    int tid = threadIdx.x, tx = tid & 15, ty = tid >> 4;
    int r0 = ty*4, c0 = tx*4;
    float acc[4][4] = {};
    const float* tmv = g_tm + p*FF;
    for (int t0 = 0; t0 < TT; t0 += 8){
        __syncthreads();
        #pragma unroll
        for (int ii = 0; ii < 2; ii++){
            int idx = ii*256 + tid;
            int s = idx >> 6, f = idx & 63;
            const float* row = sf + ((size_t)p*TT + t0 + s)*FF;
            af[s][f] = row[tf*64 + f] - tmv[tf*64 + f];
            ag[s][f] = row[tg*64 + f] - tmv[tg*64 + f];
        }
        __syncthreads();
        #pragma unroll
        for (int s = 0; s < 8; s++){
            float a[4], b[4];
            #pragma unroll
            for (int i = 0; i < 4; i++) a[i] = af[s][r0+i];
            #pragma unroll
            for (int j = 0; j < 4; j++) b[j] = ag[s][c0+j];
            #pragma unroll
            for (int i = 0; i < 4; i++)
                #pragma unroll
                for (int j = 0; j < 4; j++) acc[i][j] += a[i]*b[j];
        }
    }
    const float inv = 1.0f/(TT-1);
    float* dst = g_task + (size_t)p*FF*FF;
    #pragma unroll
    for (int i = 0; i < 4; i++)
        #pragma unroll
        for (int j = 0; j < 4; j++){
            int fr = tf*64 + r0 + i, gc = tg*64 + c0 + j;
            float v = acc[i][j]*inv;
            dst[(size_t)fr*FF + gc] = v;
            dst[(size_t)gc*FF + fr] = v;
        }
}

// ------------------------- cov_reg -------------------------
__global__ void buildM_k(const float* __restrict__ sf){
    int tile = blockIdx.x;          // 0..35
    int pc   = blockIdx.y;
    int p = pc / CC, c = pc % CC;
    int tf = 0, rem = tile;
    while (rem >= tf+1){ rem -= tf+1; tf++; }
    int tg = rem;
    __shared__ float af[4][68], ag[4][68];
    int tid = threadIdx.x, tx = tid & 15, ty = tid >> 4;
    int r0 = ty*4, c0 = tx*4;
    float acc[4][4] = {};
    int n = g_cnt[c];
    const float* mu = g_means + (size_t)pc*FF;
    for (int m0 = 0; m0 < n; m0 += 4){
        __syncthreads();
        {
            int s = tid >> 6, f = tid & 63;
            int m = m0 + s;
            float va = 0.0f, vg = 0.0f;
            if (m < n){
                int t = g_members[c*TT + m];
                const float* row = sf + ((size_t)p*TT + t)*FF;
                va = row[tf*64 + f] - mu[tf*64 + f];
                vg = row[tg*64 + f] - mu[tg*64 + f];
            }
            af[s][f] = va; ag[s][f] = vg;
        }
        __syncthreads();
        #pragma unroll
        for (int s = 0; s < 4; s++){
            float a[4], b[4];
            #pragma unroll
            for (int i = 0; i < 4; i++) a[i] = af[s][r0+i];
            #pragma unroll
            for (int j = 0; j < 4; j++) b[j] = ag[s][c0+j];
            #pragma unroll
            for (int i = 0; i < 4; i++)
                #pragma unroll
                for (int j = 0; j < 4; j++) acc[i][j] += a[i]*b[j];
        }
    }
    float ss = g_sclS[c], st = g_sclT[c];
    float* dst = g_M + (size_t)pc*FF*FF;
    const float* tk = g_task + (size_t)p*FF*FF;
    #pragma unroll
    for (int i = 0; i < 4; i++)
        #pragma unroll
        for (int j = 0; j < 4; j++){
            int fr = tf*64 + r0 + i, gc = tg*64 + c0 + j;
            float v = ss*acc[i][j] + st*tk[(size_t)fr*FF + gc] + ((fr == gc) ? 1.0f : 0.0f);
            dst[(size_t)fr*FF + gc] = v;
            dst[(size_t)gc*FF + fr] = v;
        }
}

// -------- zero Wh upper blocks + g_quad in one launch --------
__global__ void zeroinit_k(){
    int b = blockIdx.x;
    if (b < 4*NM){
        int rb = b & 3, mat = b >> 2;
        uint32_t* wh = g_Wh + (size_t)mat*FF*(FF/2);
        for (int e = threadIdx.x; e < 64*32; e += 256){
            int r = e >> 5, cp = e & 31;
            size_t o = (size_t)(rb*128 + r)*(FF/2) + rb*64 + 32 + cp;
            wh[o] = 0u;
        }
    } else {
        int bb = b - 4*NM;
        size_t base = (size_t)bb*256;
        size_t n = (size_t)PP*QQ*CC;
        for (size_t i = base + threadIdx.x; i < n; i += (size_t)640*256)
            g_quad[i] = 0.0f;
    }
}

// ================== fp16 3-term 64x64x64 tile GEMM machinery ==================
#define WP 36
__device__ __forceinline__ void stg_split(uint32_t* dh, uint32_t* dl,
                                          const float* g, int tid){
    #pragma unroll
    for (int e = tid; e < 2048; e += 256){
        int r = e >> 5, kp = e & 31;
        float2 v = *(const float2*)&g[(size_t)r*FF + 2*kp];
        uint32_t hi, lo; split2f(v.x, v.y, hi, lo);
        dh[r*WP + kp] = hi; dl[r*WP + kp] = lo;
    }
}
__device__ __forceinline__ void stg_splitT(uint32_t* dh, uint32_t* dl,
                                           const float* g, int tid){
    #pragma unroll
    for (int e = tid; e < 2048; e += 256){
        int n = e & 63, kp = e >> 6;
        float x0 = g[(size_t)(2*kp)*FF + n];
        float x1 = g[(size_t)(2*kp+1)*FF + n];
        uint32_t hi, lo; split2f(x0, x1, hi, lo);
        dh[n*WP + kp] = hi; dl[n*WP + kp] = lo;
    }
}
__device__ __forceinline__ void stg_splitT_s(uint32_t* dh, uint32_t* dl,
                                             const float* s, int tid){
    #pragma unroll
    for (int e = tid; e < 2048; e += 256){
        int n = e & 63, kp = e >> 6;
        uint32_t hi, lo; split2f(s[(2*kp)*65 + n], s[(2*kp+1)*65 + n], hi, lo);
        dh[n*WP + kp] = hi; dl[n*WP + kp] = lo;
    }
}
// split from shared fp32 pitch-68 source (rows as-is)
__device__ __forceinline__ void stg_split_s68(uint32_t* dh, uint32_t* dl,
                                              const float* s, int tid){
    #pragma unroll
    for (int e = tid; e < 2048; e += 256){
        int r = e >> 5, kp = e & 31;
        uint32_t hi, lo; split2f(s[r*68 + 2*kp], s[r*68 + 2*kp + 1], hi, lo);
        dh[r*WP + kp] = hi; dl[r*WP + kp] = lo;
    }
}
// C(16x32 per warp) += A * B^T, 3-term fp16. warpM 0..3, warpN 0..1.
// tri: skip output blocks strictly above the diagonal (for kk==i trailing tiles).
__device__ __forceinline__ void h64nt3(uint32_t sAh_b, uint32_t sAl_b,
                                       uint32_t sBh_b, uint32_t sBl_b,
                                       float acc[4][4], int warpM, int warpN,
                                       int lm_row, int lm_col, bool tri){
    #pragma unroll
    for (int s = 0; s < 4; s++){
        uint32_t aoff = (uint32_t)(((warpM*16 + lm_row)*WP + 8*s + lm_col)*4);
        uint32_t ah0,ah1,ah2,ah3, al0,al1,al2,al3;
        ldm4(ah0,ah1,ah2,ah3, sAh_b + aoff);
        ldm4(al0,al1,al2,al3, sAl_b + aoff);
        #pragma unroll
        for (int bn = 0; bn < 2; bn++){
            if (tri && (warpN*32 + bn*16) > (warpM*16 + 15)) continue;
            uint32_t boff = (uint32_t)(((warpN*32 + bn*16 + lm_row)*WP + 8*s + lm_col)*4);
            uint32_t bh0,bh1,bh2,bh3, bl0,bl1,bl2,bl3;
            ldm4(bh0,bh1,bh2,bh3, sBh_b + boff);
            ldm4(bl0,bl1,bl2,bl3, sBl_b + boff);
            MMA_F16(acc[bn*2],   ah0,ah1,ah2,ah3, bh0,bh2);
            MMA_F16(acc[bn*2],   ah0,ah1,ah2,ah3, bl0,bl2);
            MMA_F16(acc[bn*2],   al0,al1,al2,al3, bh0,bh2);
            MMA_F16(acc[bn*2+1], ah0,ah1,ah2,ah3, bh1,bh3);
            MMA_F16(acc[bn*2+1], ah0,ah1,ah2,ah3, bl1,bl3);
            MMA_F16(acc[bn*2+1], al0,al1,al2,al3, bh1,bh3);
        }
    }
}

#define PTW 68

// -------------- Phase A step j: diag factor + tri-inverse + fp16 panel --------
// smem: sA (64*68 f), sB (64*68 f), then 4 split arrays (64*36 u32)
#define DP_SMEM (2*64*PTW*4 + 4*64*WP*4)
__global__ void __launch_bounds__(256) diagpanel_k(int j){
    extern __shared__ float sm[];
    float* sA = sm;
    float* sB = sm + 64*PTW;
    uint32_t* sBh = (uint32_t*)(sm + 2*64*PTW);
    uint32_t* sBl = sBh + 64*WP;
    uint32_t* sAh = sBl + 64*WP;
    uint32_t* sAl = sAh + 64*WP;
    int mat = blockIdx.x;
    float* M = g_M + (size_t)mat*FF*FF;
    float* W = g_W + (size_t)mat*FF*FF;
    int tid = threadIdx.x, lane = tid & 31, wid = tid >> 5;
    int g = lane >> 2, tt = lane & 3;
    int warpM = wid & 3, warpN = wid >> 2;
    int lm_row = (lane & 7) + ((lane >> 3) & 1)*8;
    int lm_col = (lane >> 4)*4;

    // load diag block (fp32, pitch 68)
    #pragma unroll
    for (int e = tid; e < 1024; e += 256){
        int r = e >> 4, c4 = e & 15;
        *(float4*)&sA[r*PTW + c4*4] = *(const float4*)&M[(size_t)(j*64 + r)*FF + j*64 + c4*4];
    }
    __syncthreads();
    // LDL^T elimination
    for (int k = 0; k < 64; k++){
        float pinv = 1.0f / sA[k*PTW+k];
        #pragma unroll 4
        for (int e = tid; e < 4096; e += 256){
            int r = e >> 6, cc = e & 63;
            if (r > k && cc > k && cc <= r)
                sA[r*PTW+cc] -= sA[r*PTW+k]*sA[cc*PTW+k]*pinv;
        }
        __syncthreads();
    }
    if (tid < 64) sB[tid] = rsqrtf(sA[tid*PTW+tid]);
    __syncthreads();
    #pragma unroll 4
    for (int e = tid; e < 4096; e += 256){
        int r = e >> 6, cc = e & 63;
        if (cc <= r) sA[r*PTW+cc] *= sB[cc];
    }
    __syncthreads();

    // triangular inverse of L_jj -> sB (4 lanes per column)
    #pragma unroll 4
    for (int e = tid; e < 4096; e += 256) sB[(e>>6)*PTW + (e&63)] = 0.0f;
    __syncthreads();
    {
        int c = tid >> 2, s = tid & 3;
        unsigned gmask = 0xFu << ((tid & 31) & ~3);
        float dv = 1.0f / sA[c*PTW+c];
        if (s == 0) sB[c*PTW+c] = dv;
        __syncwarp(gmask);
        for (int r = c+1; r < 64; r++){
            float part = 0.0f;
            for (int k2 = c + s; k2 < r; k2 += 4)
                part += sA[r*PTW+k2] * sB[k2*PTW+c];
            part += __shfl_xor_sync(gmask, part, 1);
            part += __shfl_xor_sync(gmask, part, 2);
            if (s == 0) sB[r*PTW+c] = -part / sA[r*PTW+r];
            __syncwarp(gmask);
        }
    }
    __syncthreads();
    // store Linv_jj into W (fp32) + fp16 pack, and split Linv_jj for panel MMA
    #pragma unroll 4
    for (int e = tid; e < 4096; e += 256){
        int r = e >> 6, cc = e & 63;
        W[(size_t)(j*64 + r)*FF + j*64 + cc] = sB[r*PTW+cc];
    }
    {
        uint32_t* wh = g_Wh + (size_t)mat*FF*(FF/2);
        for (int e = tid; e < 2048; e += 256){
            int r = e >> 5, cp = e & 31;
            size_t o = (size_t)(j*64 + r)*(FF/2) + j*32 + cp;
            wh[o] = pack_h2(sB[r*PTW + 2*cp], sB[r*PTW + 2*cp + 1]);
        }
    }
    stg_split_s68(sBh, sBl, sB, tid);
    __syncthreads();
    // panel: L_ij = A_ij * Linv_jj^T  (fp16 3-term)
    uint32_t sAh_b = smem_u32(sAh), sAl_b = smem_u32(sAl);
    uint32_t sBh_b = smem_u32(sBh), sBl_b = smem_u32(sBl);
    for (int i = j+1; i < 8; i++){
        stg_split(sAh, sAl, M + (size_t)(i*64)*FF + j*64, tid);
        __syncthreads();
        float acc[4][4] = {};
        h64nt3(sAh_b, sAl_b, sBh_b, sBl_b, acc, warpM, warpN, lm_row, lm_col, false);
        #pragma unroll
        for (int ni = 0; ni < 4; ni++){
            int cbase = j*64 + warpN*32 + ni*8 + 2*tt;
            int r0 = i*64 + warpM*16 + g;
            float2 v0 = {acc[ni][0], acc[ni][1]};
            float2 v1 = {acc[ni][2], acc[ni][3]};
            *(float2*)&M[(size_t)r0*FF + cbase] = v0;
            *(float2*)&M[(size_t)(r0+8)*FF + cbase] = v1;
        }
        __syncthreads();
    }
}

// -------------- Phase A trailing: fp16 3-term MMA -------------
#define TR_SMEM (4*64*WP*4)
__global__ void __launch_bounds__(256) trailing_k(int j){
    extern __shared__ uint32_t su[];
    uint32_t* sAh = su;
    uint32_t* sAl = sAh + 64*WP;
    uint32_t* sBh = sAl + 64*WP;
    uint32_t* sBl = sBh + 64*WP;
    int mat = blockIdx.y;
    int t = blockIdx.x;
    int i = j+1, cnt = 1;
    while (t >= cnt){ t -= cnt; i++; cnt = i - j; }
    int kk = j+1 + t;
    float* M = g_M + (size_t)mat*FF*FF;
    int tid = threadIdx.x, lane = tid & 31, wid = tid >> 5;
    int g = lane >> 2, tt = lane & 3;
    int warpM = wid & 3, warpN = wid >> 2;
    int lm_row = (lane & 7) + ((lane >> 3) & 1)*8;
    int lm_col = (lane >> 4)*4;
    bool tri = (kk == i);

    stg_split(sAh, sAl, M + (size_t)(i*64)*FF + j*64, tid);
    stg_split(sBh, sBl, M + (size_t)(kk*64)*FF + j*64, tid);
    __syncthreads();
    float acc[4][4] = {};
    h64nt3(smem_u32(sAh), smem_u32(sAl), smem_u32(sBh), smem_u32(sBl),
           acc, warpM, warpN, lm_row, lm_col, tri);
    #pragma unroll
    for (int ni = 0; ni < 4; ni++){
        int cb = warpN*32 + ni*8 + 2*tt;
        if (tri && cb > warpM*16 + 15) continue;
        int cbase = kk*64 + cb;
        int r0 = i*64 + warpM*16 + g;
        float2* p0 = (float2*)&M[(size_t)r0*FF + cbase];
        float2 v0 = *p0; v0.x -= acc[ni][0]; v0.y -= acc[ni][1]; *p0 = v0;
        float2* p1 = (float2*)&M[(size_t)(r0+8)*FF + cbase];
        float2 v1 = *p1; v1.x -= acc[ni][2]; v1.y -= acc[ni][3]; *p1 = v1;
    }
}

// -------------- Phase B: fp16 3-term MMA (NN via transpose staging) -------------
#define PB_SMEM (4*64*WP*4 + 64*65*4)
__global__ void __launch_bounds__(256) phaseB_k(){
    extern __shared__ uint32_t su[];
    uint32_t* sAh = su;
    uint32_t* sAl = sAh + 64*WP;
    uint32_t* sBh = sAl + 64*WP;
    uint32_t* sBl = sBh + 64*WP;
    float*    sC  = (float*)(sBl + 64*WP);
    int j   = blockIdx.x;
    int mat = blockIdx.y;
    float* M = g_M + (size_t)mat*FF*FF;
    float* W = g_W + (size_t)mat*FF*FF;
    uint32_t* wh = g_Wh + (size_t)mat*FF*(FF/2);
    int tid = threadIdx.x, lane = tid & 31, wid = tid >> 5;
    int g = lane >> 2, tt = lane & 3;
    int warpM = wid & 3, warpN = wid >> 2;
    int lm_row = (lane & 7) + ((lane >> 3) & 1)*8;
    int lm_col = (lane >> 4)*4;
    uint32_t sAh_b = smem_u32(sAh), sAl_b = smem_u32(sAl);
    uint32_t sBh_b = smem_u32(sBh), sBl_b = smem_u32(sBl);

    for (int i = j+1; i < 8; i++){
        float acc[4][4] = {};
        for (int k = j; k < i; k++){
            __syncthreads();
            stg_split (sAh, sAl, M + (size_t)(i*64)*FF + k*64, tid);
            stg_splitT(sBh, sBl, W + (size_t)(k*64)*FF + j*64, tid);
            __syncthreads();
            h64nt3(sAh_b, sAl_b, sBh_b, sBl_b, acc, warpM, warpN, lm_row, lm_col, false);
        }
        __syncthreads();
        #pragma unroll
        for (int ni = 0; ni < 4; ni++){
            int cbase = warpN*32 + ni*8 + 2*tt;
            int r0 = warpM*16 + g;
            sC[r0*65 + cbase]     = acc[ni][0];
            sC[r0*65 + cbase + 1] = acc[ni][1];
            sC[(r0+8)*65 + cbase]     = acc[ni][2];
            sC[(r0+8)*65 + cbase + 1] = acc[ni][3];
        }
        __syncthreads();
        stg_split  (sAh, sAl, W + (size_t)(i*64)*FF + i*64, tid);
        stg_splitT_s(sBh, sBl, sC, tid);
        __syncthreads();
        float acc2[4][4] = {};
        h64nt3(sAh_b, sAl_b, sBh_b, sBl_b, acc2, warpM, warpN, lm_row, lm_col, false);
        #pragma unroll
        for (int ni = 0; ni < 4; ni++){
            int cbase = warpN*32 + ni*8 + 2*tt;
            #pragma unroll
            for (int h = 0; h < 2; h++){
                int row = i*64 + warpM*16 + g + h*8;
                float v0 = -acc2[ni][h*2], v1 = -acc2[ni][h*2+1];
                float2 v = {v0, v1};
                *(float2*)&W[(size_t)row*FF + j*64 + cbase] = v;
                wh[(size_t)row*(FF/2) + j*32 + (cbase >> 1)] = pack_h2(v0, v1);
            }
        }
        __syncthreads();
    }
}

// ------------------------- queries -> fp16 pairs, transposed -------------------------
__global__ void qsplit_k(const float* __restrict__ qf){
    __shared__ float sq[16][FF];
    int qb = blockIdx.x;
    int p  = blockIdx.y;
    int tid = threadIdx.x;
    for (int u = tid; u < 16*FF; u += 256){
        int qi = u / FF, f = u % FF;
        sq[qi][f] = qf[((size_t)p*QQ + qb*16 + qi)*FF + f];
    }
    __syncthreads();
    uint32_t* dh = g_Xh + (size_t)p*(FF/2)*QQ;
    for (int u = tid; u < 256*16; u += 256){
        int kp = u >> 4, qi = u & 15;
        dh[(size_t)kp*QQ + qb*16 + qi] = pack_h2(sq[qi][2*kp], sq[qi][2*kp+1]);
    }
}

// ------------------------- y = W * mu (fp32 exact, triangular) -------------------------
__global__ void ymu_k(){
    __shared__ float smu[FF];
    int pc = blockIdx.x;
    int tid = threadIdx.x, lane = tid & 31, wid = tid >> 5;
    const float* W = g_W + (size_t)pc*FF*FF;
    for (int f = tid; f < FF; f += 256) smu[f] = g_means[(size_t)pc*FF + f];
    __syncthreads();
    for (int r = wid; r < FF; r += 8){
        float s = 0.0f;
        for (int k = lane; k <= r; k += 32)
            s += W[(size_t)r*FF + k] * smu[k];
        #pragma unroll
        for (int o = 16; o; o >>= 1) s += __shfl_xor_sync(0xFFFFFFFFu, s, o);
        if (lane == 0) g_Ymu[pc*FF + r] = s;
    }
}

// ===== quad via single fp16 mma.sync, double-buffered =====
#define WPITCH 36
#define XPITCH 136
#define BUFU (128*WPITCH + 32*XPITCH)
#define QMMA_SMEM (2*BUFU*4 + 128*4)
__device__ __forceinline__ void stageWX(uint32_t* sW, uint32_t* sX,
                                        const uint4* gw, const uint4* gx,
                                        int rb, int kp0, int tid){
    #pragma unroll
    for (int u = tid; u < 1024; u += 256){
        int r = u >> 3, c4 = u & 7;
        *(uint4*)&sW[r*WPITCH + c4*4] = gw[(size_t)(rb*128 + r)*(FF/8) + (kp0 >> 2) + c4];
    }
    #pragma unroll
    for (int u = tid; u < 1024; u += 256){
        int kp = u >> 5, q4 = u & 31;
        *(uint4*)&sX[kp*XPITCH + q4*4] = gx[(size_t)(kp0 + kp)*(QQ/4) + q4];
    }
}
__global__ void __launch_bounds__(256, 2) quadmma_k(){
    extern __shared__ uint32_t smu32[];
    uint32_t* sW0 = smu32;
    uint32_t* sX0 = sW0 + 128*WPITCH;
    uint32_t* sW1 = smu32 + BUFU;
    uint32_t* sX1 = sW1 + 128*WPITCH;
    float*    red = (float*)(smu32 + 2*BUFU);
    int pc = blockIdx.y;
    int p = pc / CC, c = pc % CC;
    int qbase = blockIdx.x * 128;
    int rb = blockIdx.z;
    int tid = threadIdx.x, lane = tid & 31, wid = tid >> 5;
    int g = lane >> 2, t = lane & 3;
    int warpM = wid & 1, warpN = wid >> 1;
    int lm_row = (lane & 7) + ((lane >> 3) & 1)*8;
    int lm_col = (lane >> 4)*4;
    uint32_t sW0_b = smem_u32(sW0), sW1_b = smem_u32(sW1);
    const uint4* gwh4 = (const uint4*)(g_Wh + (size_t)pc*FF*(FF/2));
    const uint4* gxh4 = (const uint4*)(g_Xh + (size_t)p*(FF/2)*QQ + qbase);
    const float* ym = g_Ymu + pc*FF;

    if (tid < 128) red[tid] = 0.0f;
    float qs[8];
    #pragma unroll
    for (int j = 0; j < 8; j++) qs[j] = 0.0f;

    float acc[4][4][4];
    #pragma unroll
    for (int mi = 0; mi < 4; mi++)
        #pragma unroll
        for (int ni = 0; ni < 4; ni++)
            #pragma unroll
            for (int r = 0; r < 4; r++) acc[mi][ni][r] = 0.0f;

    int nch = 2*rb + 2;
    stageWX(sW0, sX0, gwh4, gxh4, rb, 0, tid);
    __syncthreads();
    for (int ch = 0; ch < nch; ch++){
        bool even = !(ch & 1);
        uint32_t* sX   = even ? sX0 : sX1;
        uint32_t  sW_b = even ? sW0_b : sW1_b;
        if (ch + 1 < nch)
            stageWX(even ? sW1 : sW0, even ? sX1 : sX0, gwh4, gxh4, rb, (ch+1)*32, tid);

        bool diag = (ch >= 2*rb);
        int kbase = (ch - 2*rb)*64;
        #pragma unroll
        for (int s = 0; s < 4; s++){
            uint32_t bh[4][2];
            #pragma unroll
            for (int ni = 0; ni < 4; ni++){
                int col = warpN*32 + ni*8 + g;
                bh[ni][0] = sX[(8*s + t)*XPITCH + col];
                bh[ni][1] = sX[(8*s + t + 4)*XPITCH + col];
            }
            #pragma unroll
            for (int mi = 0; mi < 4; mi++){
                if (diag && (warpM*64 + mi*16 + 16 <= kbase + 16*s)) continue;
                uint32_t off = (uint32_t)(((warpM*64 + mi*16 + lm_row)*WPITCH + 8*s + lm_col)*4);
                uint32_t ah0,ah1,ah2,ah3;
                ldm4(ah0,ah1,ah2,ah3, sW_b + off);
                #pragma unroll
                for (int ni = 0; ni < 4; ni++)
                    MMA_F16(acc[mi][ni], ah0,ah1,ah2,ah3, bh[ni][0],bh[ni][1]);
            }
        }
        __syncthreads();
    }
    #pragma unroll
    for (int mi = 0; mi < 4; mi++){
        int r1 = rb*128 + warpM*64 + mi*16 + g;
        float y1 = ym[r1], y2 = ym[r1 + 8];
        #pragma unroll
        for (int ni = 0; ni < 4; ni++){
            float d0 = y1 - acc[mi][ni][0];
            float d1 = y1 - acc[mi][ni][1];
            float d2 = y2 - acc[mi][ni][2];
            float d3 = y2 - acc[mi][ni][3];
            qs[2*ni]   += d0*d0 + d2*d2;
            qs[2*ni+1] += d1*d1 + d3*d3;
        }
    }
    #pragma unroll
    for (int j = 0; j < 8; j++)
        #pragma unroll
        for (int o = 4; o < 32; o <<= 1)
            qs[j] += __shfl_xor_sync(0xFFFFFFFFu, qs[j], o);
    if (lane < 4){
        #pragma unroll
        for (int j = 0; j < 8; j++){
            int ni = j >> 1, b = j & 1;
            int q = warpN*32 + ni*8 + 2*lane + b;
            atomicAdd(&red[q], qs[j]);
        }
    }
    __syncthreads();
    if (tid < 128)
        atomicAdd(&g_quad[((size_t)p*QQ + qbase + tid)*CC + c], red[tid]);
}

// ------------------------- final outputs -------------------------
__global__ void logits_k(float* out){
    int q = blockIdx.x;
    int c = threadIdx.x;
    if (c < CC){
        float s = 0.0f;
        #pragma unroll
        for (int p = 0; p < PP; p++) s += g_quad[((size_t)p*QQ + q)*CC + c];
        out[q*CC + c] = -s * (1.0f/PP);
    }
}
__global__ void copymeans_k(float* out){
    for (int i = blockIdx.x*blockDim.x + threadIdx.x; i < NM*FF; i += gridDim.x*blockDim.x)
        out[QQ*CC + i] = g_means[i];
}

// ------------------------- launch -------------------------
extern "C" void kernel_launch(void* const* d_in, const int* in_sizes, int n_in,
                              void* d_out, int out_size) {
    const float* sf  = (const float*)d_in[0];
    const int*   lab = (const int*)d_in[1];
    const float* qf  = (const float*)d_in[2];
    float* out = (float*)d_out;

    cudaFuncSetAttribute(diagpanel_k, cudaFuncAttributeMaxDynamicSharedMemorySize, DP_SMEM);
    cudaFuncSetAttribute(phaseB_k,    cudaFuncAttributeMaxDynamicSharedMemorySize, PB_SMEM);
    cudaFuncSetAttribute(trailing_k,  cudaFuncAttributeMaxDynamicSharedMemorySize, TR_SMEM);
    cudaFuncSetAttribute(quadmma_k,   cudaFuncAttributeMaxDynamicSharedMemorySize, QMMA_SMEM);

    setup_k<<<1, 32>>>(lab);
    means_k<<<NM, 256>>>(sf);
    tm_k<<<PP, 256>>>(sf);
    qsplit_k<<<dim3(64, PP), 256>>>(qf);
    taskcov_k<<<dim3(36, PP), 256>>>(sf);
    buildM_k<<<dim3(36, NM), 256>>>(sf);
    zeroinit_k<<<4*NM + 640, 256>>>();
    for (int j = 0; j < 8; j++){
        diagpanel_k<<<NM, 256, DP_SMEM>>>(j);
        int nt = (7-j)*(8-j)/2;
        if (nt > 0)
            trailing_k<<<dim3(nt, NM), 256, TR_SMEM>>>(j);
    }
    phaseB_k<<<dim3(7, NM), 256, PB_SMEM>>>();
    ymu_k<<<NM, 256>>>();
    quadmma_k<<<dim3(8, NM, 4), 256, QMMA_SMEM>>>();
    logits_k<<<QQ, 32>>>(out);
    if (out_size >= QQ*CC + NM*FF)
        copymeans_k<<<160, 512>>>(out);
}